// round 13
// baseline (speedup 1.0000x reference)
#include <cuda_runtime.h>
#include <cuda_bf16.h>
#include <cstdint>

#define DIM   512
#define HEADS 16
#define HD    32
#define SS    49
#define BTOT  2048
#define MROWS (BTOT * SS)   // 100352 = 784 * 128
#define KDIM  512
#define QSCALE 0.17677669529663687f

// ---------------- scratch (__device__ globals; allocation-free rule) -------
__device__ __nv_bfloat16 g_xh[(size_t)MROWS * KDIM];
__device__ __nv_bfloat16 g_xl[(size_t)MROWS * KDIM];
__device__ __nv_bfloat16 g_qkvh[(size_t)MROWS * 3 * DIM];  // split qkv hi
__device__ __nv_bfloat16 g_qkvl[(size_t)MROWS * 3 * DIM];  // split qkv lo
__device__ __nv_bfloat16 g_ah[(size_t)MROWS * DIM];
__device__ __nv_bfloat16 g_al[(size_t)MROWS * DIM];
__device__ __nv_bfloat16 g_wqh[(size_t)3 * DIM * KDIM];   // transposed [1536][512]
__device__ __nv_bfloat16 g_wql[(size_t)3 * DIM * KDIM];
__device__ __nv_bfloat16 g_wph[(size_t)DIM * KDIM];       // transposed [512][512]
__device__ __nv_bfloat16 g_wpl[(size_t)DIM * KDIM];
__device__ float         g_bq[3 * DIM];                   // q-scaled qkv bias
__device__ float         g_bm[4 * HEADS * SS * SS];       // bias+mask table

// ---------------- PTX helpers ---------------------------------------------
__device__ __forceinline__ uint32_t smem_u32(const void* p) {
    uint32_t a;
    asm("{ .reg .u64 t; cvta.to.shared.u64 t, %1; cvt.u32.u64 %0, t; }"
        : "=r"(a) : "l"(p));
    return a;
}
__device__ __forceinline__ void cpa16(uint32_t s, const void* g) {
    asm volatile("cp.async.cg.shared.global [%0], [%1], 16;" :: "r"(s), "l"(g));
}
#define CP_COMMIT() asm volatile("cp.async.commit_group;")
#define CP_WAIT1()  asm volatile("cp.async.wait_group 1;")
#define CP_WAIT0()  asm volatile("cp.async.wait_group 0;")

#define LDSM4(r, addr) \
    asm volatile("ldmatrix.sync.aligned.m8n8.x4.shared.b16 {%0,%1,%2,%3}, [%4];" \
        : "=r"((r)[0]), "=r"((r)[1]), "=r"((r)[2]), "=r"((r)[3]) : "r"(addr))

#define LDSM4T(r, addr) \
    asm volatile("ldmatrix.sync.aligned.m8n8.x4.trans.shared.b16 {%0,%1,%2,%3}, [%4];" \
        : "=r"((r)[0]), "=r"((r)[1]), "=r"((r)[2]), "=r"((r)[3]) : "r"(addr))

#define MMA16816(d, a, b0, b1) \
    asm volatile("mma.sync.aligned.m16n8k16.row.col.f32.bf16.bf16.f32 " \
        "{%0,%1,%2,%3}, {%4,%5,%6,%7}, {%8,%9}, {%0,%1,%2,%3};" \
        : "+f"((d)[0]), "+f"((d)[1]), "+f"((d)[2]), "+f"((d)[3]) \
        : "r"((a)[0]), "r"((a)[1]), "r"((a)[2]), "r"((a)[3]), "r"(b0), "r"(b1))

// ---------------------------------------------------------------------------
// Split-precision HMMA GEMM (R12-proven mainloop): C = (Ah+Al)@(Bh+Bl)^T + bias
// splitOut=1: write (hi,lo) bf16 arrays; splitOut=0: write fp32.
// ---------------------------------------------------------------------------
#define TSTRIDE     64                       // bytes/row: 32 bf16, no pad
#define TILE_BYTES  (128 * TSTRIDE)          // 8192
#define STAGE_BYTES (4 * TILE_BYTES)         // 32768 (Ah,Al,Bh,Bl)
#define GEMM_SMEM   (3 * STAGE_BYTES)        // 98304

__global__ __launch_bounds__(256, 2) void gemm_bf16x3_mma(
    const __nv_bfloat16* __restrict__ Ah, const __nv_bfloat16* __restrict__ Al,
    const __nv_bfloat16* __restrict__ Bh, const __nv_bfloat16* __restrict__ Bl,
    const float* __restrict__ bias, float* __restrict__ Cf,
    __nv_bfloat16* __restrict__ Chi, __nv_bfloat16* __restrict__ Clo,
    int N, int splitOut)
{
    extern __shared__ char smem[];
    const uint32_t sb = smem_u32(smem);
    const int tid  = threadIdx.x;
    const int lane = tid & 31, wid = tid >> 5;
    const int wr = wid >> 2, wc = wid & 3;        // warp grid 2x4
    const long m0 = (long)blockIdx.y * 128;
    const int  n0 = blockIdx.x * 128;

    auto load_stage = [&](int s, int k0) {
        const uint32_t base = sb + (uint32_t)s * STAGE_BYTES;
        #pragma unroll
        for (int half = 0; half < 2; half++) {
            const int chunk = tid + half * 256;
            const int r = chunk >> 2, c = chunk & 3;
            const int cs = c ^ ((r >> 1) & 3);          // swizzled chunk
            const uint32_t off = (uint32_t)r * TSTRIDE + cs * 16;
            const long aIdx = (m0 + r) * (long)KDIM + k0 + c * 8;
            const long bIdx = ((long)n0 + r) * (long)KDIM + k0 + c * 8;
            cpa16(base + off,                  (const char*)(Ah + aIdx));
            cpa16(base + TILE_BYTES + off,     (const char*)(Al + aIdx));
            cpa16(base + 2 * TILE_BYTES + off, (const char*)(Bh + bIdx));
            cpa16(base + 3 * TILE_BYTES + off, (const char*)(Bl + bIdx));
        }
    };

    float acc[4][4][4];
    #pragma unroll
    for (int mi = 0; mi < 4; mi++)
        #pragma unroll
        for (int ni = 0; ni < 4; ni++)
            #pragma unroll
            for (int j = 0; j < 4; j++) acc[mi][ni][j] = 0.f;

    const int sA = ((lane & 15) >> 1) & 3;
    const int bg = lane >> 3, bfr = bg >> 1, bkh = bg & 1;
    const int sB = ((lane & 7) >> 1) & 3;
    const uint32_t cA[2] = { (uint32_t)(((lane >> 4) ^ sA) * 16),
                             (uint32_t)(((2 + (lane >> 4)) ^ sA) * 16) };
    const uint32_t cB[2] = { (uint32_t)((bkh ^ sB) * 16),
                             (uint32_t)(((2 + bkh) ^ sB) * 16) };
    const uint32_t aRowOff = (uint32_t)(wr * 64 + (lane & 15)) * TSTRIDE;
    const uint32_t bRowOff = 2 * TILE_BYTES +
        (uint32_t)(wc * 32 + bfr * 8 + (lane & 7)) * TSTRIDE;

    auto compute_stage = [&](int s) {
        const uint32_t base = sb + (uint32_t)s * STAGE_BYTES;
        #pragma unroll
        for (int kk = 0; kk < 2; kk++) {
            uint32_t bh[2][4], bl[2][4];
            #pragma unroll
            for (int p = 0; p < 2; p++) {
                uint32_t addr = base + bRowOff + (uint32_t)p * 16 * TSTRIDE + cB[kk];
                LDSM4(bh[p], addr);
                LDSM4(bl[p], addr + TILE_BYTES);
            }
            #pragma unroll
            for (int mi = 0; mi < 4; mi++) {
                uint32_t aaddr = base + aRowOff + (uint32_t)mi * 16 * TSTRIDE + cA[kk];
                uint32_t ah[4];
                LDSM4(ah, aaddr);
                #pragma unroll
                for (int p = 0; p < 2; p++)
                    #pragma unroll
                    for (int q2 = 0; q2 < 2; q2++) {
                        const int ni = p * 2 + q2, rb = q2 * 2;
                        MMA16816(acc[mi][ni], ah, bh[p][rb], bh[p][rb + 1]);
                        MMA16816(acc[mi][ni], ah, bl[p][rb], bl[p][rb + 1]);
                    }
                uint32_t al[4];
                LDSM4(al, aaddr + TILE_BYTES);
                #pragma unroll
                for (int p = 0; p < 2; p++)
                    #pragma unroll
                    for (int q2 = 0; q2 < 2; q2++) {
                        const int ni = p * 2 + q2, rb = q2 * 2;
                        MMA16816(acc[mi][ni], al, bh[p][rb], bh[p][rb + 1]);
                    }
            }
        }
    };

    load_stage(0, 0);  CP_COMMIT();
    load_stage(1, 32); CP_COMMIT();
    #pragma unroll 1
    for (int kt = 0; kt < 16; kt++) {
        if (kt < 15) { CP_WAIT1(); } else { CP_WAIT0(); }
        __syncthreads();
        if (kt + 2 < 16) {
            load_stage((kt + 2) % 3, (kt + 2) * 32);
            CP_COMMIT();
        }
        compute_stage(kt % 3);
    }

    const int r0 = lane >> 2, cpos = (lane & 3) * 2;
    #pragma unroll
    for (int ni = 0; ni < 4; ni++) {
        const int col = n0 + wc * 32 + ni * 8 + cpos;
        const float bx = bias[col], by = bias[col + 1];
        #pragma unroll
        for (int mi = 0; mi < 4; mi++) {
            const long row = m0 + wr * 64 + mi * 16 + r0;
            float v0x = acc[mi][ni][0] + bx, v0y = acc[mi][ni][1] + by;
            float v1x = acc[mi][ni][2] + bx, v1y = acc[mi][ni][3] + by;
            if (!splitOut) {
                *(float2*)&Cf[row * (long)N + col]       = make_float2(v0x, v0y);
                *(float2*)&Cf[(row + 8) * (long)N + col] = make_float2(v1x, v1y);
            } else {
                __nv_bfloat16 h0 = __float2bfloat16(v0x), h1 = __float2bfloat16(v0y);
                __nv_bfloat16 h2 = __float2bfloat16(v1x), h3 = __float2bfloat16(v1y);
                *(__nv_bfloat162*)&Chi[row * (long)N + col] = __nv_bfloat162(h0, h1);
                *(__nv_bfloat162*)&Chi[(row + 8) * (long)N + col] = __nv_bfloat162(h2, h3);
                *(__nv_bfloat162*)&Clo[row * (long)N + col] = __nv_bfloat162(
                    __float2bfloat16(v0x - __bfloat162float(h0)),
                    __float2bfloat16(v0y - __bfloat162float(h1)));
                *(__nv_bfloat162*)&Clo[(row + 8) * (long)N + col] = __nv_bfloat162(
                    __float2bfloat16(v1x - __bfloat162float(h2)),
                    __float2bfloat16(v1y - __bfloat162float(h3)));
            }
        }
    }
}

// ---------------------------------------------------------------------------
// split / prep kernels
// ---------------------------------------------------------------------------
__global__ void split_kernel(const float* __restrict__ in,
                             __nv_bfloat16* __restrict__ hi,
                             __nv_bfloat16* __restrict__ lo, long n4)
{
    long i = (long)blockIdx.x * blockDim.x + threadIdx.x;
    const long stride = (long)gridDim.x * blockDim.x;
    for (; i < n4; i += stride) {
        float4 v = ((const float4*)in)[i];
        __nv_bfloat16 h0 = __float2bfloat16(v.x);
        __nv_bfloat16 h1 = __float2bfloat16(v.y);
        __nv_bfloat16 h2 = __float2bfloat16(v.z);
        __nv_bfloat16 h3 = __float2bfloat16(v.w);
        __nv_bfloat162* hp = (__nv_bfloat162*)hi + 2 * i;
        hp[0] = __nv_bfloat162(h0, h1);
        hp[1] = __nv_bfloat162(h2, h3);
        __nv_bfloat162* lp = (__nv_bfloat162*)lo + 2 * i;
        lp[0] = __nv_bfloat162(__float2bfloat16(v.x - __bfloat162float(h0)),
                               __float2bfloat16(v.y - __bfloat162float(h1)));
        lp[1] = __nv_bfloat162(__float2bfloat16(v.z - __bfloat162float(h2)),
                               __float2bfloat16(v.w - __bfloat162float(h3)));
    }
}

// transpose + split weights; cols n < scaleCols get q-scale folded in
__global__ void wsplit_kernel(const float* __restrict__ w,
                              __nv_bfloat16* __restrict__ hi,
                              __nv_bfloat16* __restrict__ lo, int N, int total,
                              int scaleCols)
{
    int i = blockIdx.x * 256 + threadIdx.x;
    if (i >= total) return;
    int k = i & (KDIM - 1);
    int n = i >> 9;
    float v = w[(long)k * N + n];
    if (n < scaleCols) v *= QSCALE;
    __nv_bfloat16 h = __float2bfloat16(v);
    hi[i] = h;
    lo[i] = __float2bfloat16(v - __bfloat162float(h));
}

__global__ void bprep_kernel(const float* __restrict__ b, float* __restrict__ o)
{
    int i = blockIdx.x * 256 + threadIdx.x;
    if (i >= 3 * DIM) return;
    float v = b[i];
    if (i < DIM) v *= QSCALE;
    o[i] = v;
}

__global__ void biasmask_kernel(const float* __restrict__ bias_table,
                                const int* __restrict__ rel_idx,
                                const float* __restrict__ mask,
                                float* __restrict__ bm)
{
    int idx = blockIdx.x * 256 + threadIdx.x;
    const int total = 4 * HEADS * SS * SS;
    if (idx >= total) return;
    int e = idx % (SS * SS);
    int h = (idx / (SS * SS)) % HEADS;
    int w = idx / (SS * SS * HEADS);
    bm[idx] = bias_table[rel_idx[e] * HEADS + h] + mask[w * SS * SS + e];
}

// ---------------------------------------------------------------------------
// MMA window attention. qkv arrives PRE-SPLIT (hi/lo bf16, q pre-scaled) so
// the load stage is pure cp.async 16B copies. 4 CTAs/SM.
// ---------------------------------------------------------------------------
#define AQH   0
#define AQL   5120
#define AKH   10240
#define AKL   15360
#define AVH   20480       // V hi, 64 rows x 80B
#define AVL   25600       // V lo
#define APH   30720
#define APL   39936
#define ATTN_SMEM 49152

__global__ __launch_bounds__(128) void attn_mma_kernel(
    const __nv_bfloat16* __restrict__ qkvh, const __nv_bfloat16* __restrict__ qkvl,
    const float* __restrict__ bm_tab,
    __nv_bfloat16* __restrict__ out_hi, __nv_bfloat16* __restrict__ out_lo)
{
    extern __shared__ char smem[];
    const uint32_t sb = smem_u32(smem);
    const int b = blockIdx.x, h = blockIdx.y;
    const int tid = threadIdx.x, lane = tid & 31, w = tid >> 5;

    // zero pads: q/k/v rows 49..63 (hi+lo), 16B data region only (4 chunks/row)
    for (int i = tid; i < 180; i += 128) {     // 15 rows x 12 (3 mats x 4 chunks)
        int r = 49 + i / 12, rem = i % 12, mat = rem >> 2, c = rem & 3;
        uint32_t off = (uint32_t)mat * 10240 + (uint32_t)r * 80 + c * 16;
        *(uint4*)(smem + off) = make_uint4(0, 0, 0, 0);
        *(uint4*)(smem + off + 5120) = make_uint4(0, 0, 0, 0);
    }

    // cp.async copy: 49 rows x 3 mats x 4 chunks, hi+lo
    const long rowBase = (long)b * SS * (3 * DIM) + h * HD;
    for (int e = tid; e < 588; e += 128) {     // 49*12
        int s = e / 12, rem = e % 12, mat = rem >> 2, c = rem & 3;
        long gidx = rowBase + (long)s * (3 * DIM) + mat * DIM + c * 8;
        uint32_t doff = (uint32_t)mat * 10240 + (uint32_t)s * 80 + c * 16;
        cpa16(sb + doff,        qkvh + gidx);
        cpa16(sb + doff + 5120, qkvl + gidx);
    }
    CP_COMMIT();
    CP_WAIT0();
    __syncthreads();

    float accs[8][4];
    #pragma unroll
    for (int ni = 0; ni < 8; ni++)
        #pragma unroll
        for (int j = 0; j < 4; j++) accs[ni][j] = 0.f;

    const uint32_t aQ = sb + AQH +
        (uint32_t)(w * 16 + (lane & 15)) * 80 + (lane >> 4) * 16;
    const int bg = lane >> 3, bfr = bg >> 1, bkh = bg & 1;
    const uint32_t bK = sb + AKH +
        (uint32_t)(bfr * 8 + (lane & 7)) * 80 + bkh * 16;

    #pragma unroll
    for (int kk = 0; kk < 2; kk++) {
        uint32_t ah[4], al[4];
        LDSM4(ah, aQ + kk * 32);
        LDSM4(al, aQ + (AQL - AQH) + kk * 32);
        #pragma unroll
        for (int p = 0; p < 4; p++) {
            uint32_t bh[4], bl[4];
            uint32_t addr = bK + (uint32_t)p * 16 * 80 + kk * 32;
            LDSM4(bh, addr);
            LDSM4(bl, addr + (AKL - AKH));
            #pragma unroll
            for (int q2 = 0; q2 < 2; q2++) {
                const int ni = p * 2 + q2, rb = q2 * 2;
                MMA16816(accs[ni], ah, bh[rb], bh[rb + 1]);
                MMA16816(accs[ni], ah, bl[rb], bl[rb + 1]);
                MMA16816(accs[ni], al, bh[rb], bh[rb + 1]);
            }
        }
    }

    const int r1 = lane >> 2, tq = lane & 3;
    const int row1 = w * 16 + r1, row2 = row1 + 8;
    {
        const float* bmr1 = bm_tab + ((long)(b & 3) * HEADS + h) * (SS * SS)
                            + (long)row1 * SS;
        const float* bmr2 = bmr1 + 8 * SS;
        const bool v1 = (row1 < SS), v2 = (row2 < SS);
        #pragma unroll
        for (int ni = 0; ni < 8; ni++) {
            const int c0 = ni * 8 + tq * 2, c1 = c0 + 1;
            if (c0 < SS) {
                if (v1) accs[ni][0] += bmr1[c0];
                if (v2) accs[ni][2] += bmr2[c0];
            } else { accs[ni][0] = -1e30f; accs[ni][2] = -1e30f; }
            if (c1 < SS) {
                if (v1) accs[ni][1] += bmr1[c1];
                if (v2) accs[ni][3] += bmr2[c1];
            } else { accs[ni][1] = -1e30f; accs[ni][3] = -1e30f; }
        }
        float m1 = -1e30f, m2 = -1e30f;
        #pragma unroll
        for (int ni = 0; ni < 8; ni++) {
            m1 = fmaxf(m1, fmaxf(accs[ni][0], accs[ni][1]));
            m2 = fmaxf(m2, fmaxf(accs[ni][2], accs[ni][3]));
        }
        m1 = fmaxf(m1, __shfl_xor_sync(0xffffffff, m1, 1));
        m1 = fmaxf(m1, __shfl_xor_sync(0xffffffff, m1, 2));
        m2 = fmaxf(m2, __shfl_xor_sync(0xffffffff, m2, 1));
        m2 = fmaxf(m2, __shfl_xor_sync(0xffffffff, m2, 2));
        float s1 = 0.f, s2 = 0.f;
        #pragma unroll
        for (int ni = 0; ni < 8; ni++) {
            accs[ni][0] = __expf(accs[ni][0] - m1);
            accs[ni][1] = __expf(accs[ni][1] - m1);
            accs[ni][2] = __expf(accs[ni][2] - m2);
            accs[ni][3] = __expf(accs[ni][3] - m2);
            s1 += accs[ni][0] + accs[ni][1];
            s2 += accs[ni][2] + accs[ni][3];
        }
        s1 += __shfl_xor_sync(0xffffffff, s1, 1);
        s1 += __shfl_xor_sync(0xffffffff, s1, 2);
        s2 += __shfl_xor_sync(0xffffffff, s2, 1);
        s2 += __shfl_xor_sync(0xffffffff, s2, 2);
        const float i1 = 1.0f / s1, i2 = 1.0f / s2;
        #pragma unroll
        for (int ni = 0; ni < 8; ni++) {
            int co = (ni * 8 + tq * 2) * 2;
            float p0 = accs[ni][0] * i1, p1 = accs[ni][1] * i1;
            float p2 = accs[ni][2] * i2, p3 = accs[ni][3] * i2;
            __nv_bfloat16 h0 = __float2bfloat16(p0), h1 = __float2bfloat16(p1);
            __nv_bfloat16 h2 = __float2bfloat16(p2), h3 = __float2bfloat16(p3);
            *(__nv_bfloat162*)(smem + APH + row1 * 144 + co) = __nv_bfloat162(h0, h1);
            *(__nv_bfloat162*)(smem + APH + row2 * 144 + co) = __nv_bfloat162(h2, h3);
            *(__nv_bfloat162*)(smem + APL + row1 * 144 + co) = __nv_bfloat162(
                __float2bfloat16(p0 - __bfloat162float(h0)),
                __float2bfloat16(p1 - __bfloat162float(h1)));
            *(__nv_bfloat162*)(smem + APL + row2 * 144 + co) = __nv_bfloat162(
                __float2bfloat16(p2 - __bfloat162float(h2)),
                __float2bfloat16(p3 - __bfloat162float(h3)));
        }
    }
    __syncthreads();

    float acco[4][4];
    #pragma unroll
    for (int ni = 0; ni < 4; ni++)
        #pragma unroll
        for (int j = 0; j < 4; j++) acco[ni][j] = 0.f;

    const uint32_t aP = sb + APH +
        (uint32_t)(w * 16 + (lane & 15)) * 144 + (lane >> 4) * 16;
    const int vt = lane >> 3, vlr = lane & 7;
    const uint32_t bVt = sb + AVH +
        (uint32_t)((vt & 1) * 8 + vlr) * 80 + (vt >> 1) * 16;

    #pragma unroll
    for (int ks = 0; ks < 4; ks++) {
        uint32_t ph_[4], pl_[4];
        LDSM4(ph_, aP + ks * 32);
        LDSM4(pl_, aP + (APL - APH) + ks * 32);
        #pragma unroll
        for (int p = 0; p < 2; p++) {
            uint32_t bh[4], bl[4];
            uint32_t addr = bVt + (uint32_t)ks * (16 * 80) + p * 32;
            LDSM4T(bh, addr);
            LDSM4T(bl, addr + (AVL - AVH));
            #pragma unroll
            for (int q2 = 0; q2 < 2; q2++) {
                const int ni = p * 2 + q2, rb = q2 * 2;
                MMA16816(acco[ni], ph_, bh[rb], bh[rb + 1]);
                MMA16816(acco[ni], ph_, bl[rb], bl[rb + 1]);
                MMA16816(acco[ni], pl_, bh[rb], bh[rb + 1]);
            }
        }
    }

    #pragma unroll
    for (int ni = 0; ni < 4; ni++) {
        const int d0 = ni * 8 + tq * 2;
        if (row1 < SS) {
            long idx = ((long)b * SS + row1) * DIM + h * HD + d0;
            __nv_bfloat16 h0 = __float2bfloat16(acco[ni][0]);
            __nv_bfloat16 h1 = __float2bfloat16(acco[ni][1]);
            *(__nv_bfloat162*)(out_hi + idx) = __nv_bfloat162(h0, h1);
            *(__nv_bfloat162*)(out_lo + idx) = __nv_bfloat162(
                __float2bfloat16(acco[ni][0] - __bfloat162float(h0)),
                __float2bfloat16(acco[ni][1] - __bfloat162float(h1)));
        }
        if (row2 < SS) {
            long idx = ((long)b * SS + row2) * DIM + h * HD + d0;
            __nv_bfloat16 h2 = __float2bfloat16(acco[ni][2]);
            __nv_bfloat16 h3 = __float2bfloat16(acco[ni][3]);
            *(__nv_bfloat162*)(out_hi + idx) = __nv_bfloat162(h2, h3);
            *(__nv_bfloat162*)(out_lo + idx) = __nv_bfloat162(
                __float2bfloat16(acco[ni][2] - __bfloat162float(h2)),
                __float2bfloat16(acco[ni][3] - __bfloat162float(h3)));
        }
    }
}

// ---------------------------------------------------------------------------
extern "C" void kernel_launch(void* const* d_in, const int* in_sizes, int n_in,
                              void* d_out, int out_size)
{
    const float* x          = (const float*)d_in[0];
    const float* mask       = (const float*)d_in[1];
    const float* w_qkv      = (const float*)d_in[2];
    const float* b_qkv      = (const float*)d_in[3];
    const float* w_proj     = (const float*)d_in[4];
    const float* b_proj     = (const float*)d_in[5];
    const float* bias_table = (const float*)d_in[6];
    const int*   rel_idx    = (const int*)d_in[7];
    float* out = (float*)d_out;

    __nv_bfloat16 *xh, *xl, *qkvh, *qkvl, *ah, *al, *wqh, *wql, *wph, *wpl;
    float *bm, *bq;
    cudaGetSymbolAddress((void**)&xh,   g_xh);
    cudaGetSymbolAddress((void**)&xl,   g_xl);
    cudaGetSymbolAddress((void**)&qkvh, g_qkvh);
    cudaGetSymbolAddress((void**)&qkvl, g_qkvl);
    cudaGetSymbolAddress((void**)&ah,   g_ah);
    cudaGetSymbolAddress((void**)&al,   g_al);
    cudaGetSymbolAddress((void**)&wqh,  g_wqh);
    cudaGetSymbolAddress((void**)&wql,  g_wql);
    cudaGetSymbolAddress((void**)&wph,  g_wph);
    cudaGetSymbolAddress((void**)&wpl,  g_wpl);
    cudaGetSymbolAddress((void**)&bm,   g_bm);
    cudaGetSymbolAddress((void**)&bq,   g_bq);

    cudaFuncSetAttribute(gemm_bf16x3_mma,
                         cudaFuncAttributeMaxDynamicSharedMemorySize, GEMM_SMEM);
    cudaFuncSetAttribute(attn_mma_kernel,
                         cudaFuncAttributeMaxDynamicSharedMemorySize, ATTN_SMEM);

    // 1) splits + prep
    {
        long n4 = (long)MROWS * KDIM / 4;
        split_kernel<<<2048, 256>>>(x, xh, xl, n4);
        wsplit_kernel<<<(3 * DIM * KDIM) / 256, 256>>>(w_qkv, wqh, wql, 3 * DIM,
                                                       3 * DIM * KDIM, DIM);
        wsplit_kernel<<<(DIM * KDIM) / 256, 256>>>(w_proj, wph, wpl, DIM,
                                                   DIM * KDIM, 0);
        bprep_kernel<<<6, 256>>>(b_qkv, bq);
        int bmtot = 4 * HEADS * SS * SS;
        biasmask_kernel<<<(bmtot + 255) / 256, 256>>>(bias_table, rel_idx, mask, bm);
    }

    // 2) QKV GEMM -> split bf16 output (q pre-scaled via weights/bias)
    {
        dim3 grid(12, 784);
        gemm_bf16x3_mma<<<grid, 256, GEMM_SMEM>>>(xh, xl, wqh, wql, bq,
                                                  nullptr, qkvh, qkvl,
                                                  3 * DIM, 1);
    }

    // 3) MMA window attention (pure cp.async loads)
    {
        dim3 grid(BTOT, HEADS);
        attn_mma_kernel<<<grid, 128, ATTN_SMEM>>>(qkvh, qkvl, bm, ah, al);
    }

    // 4) Proj GEMM -> fp32 output
    {
        dim3 grid(4, 784);
        gemm_bf16x3_mma<<<grid, 256, GEMM_SMEM>>>(ah, al, wph, wpl, b_proj,
                                                  out, nullptr, nullptr,
                                                  DIM, 0);
    }
}

// round 14
// speedup vs baseline: 1.0866x; 1.0866x over previous
#include <cuda_runtime.h>
#include <cuda_bf16.h>
#include <cstdint>

#define DIM   512
#define HEADS 16
#define HD    32
#define SS    49
#define BTOT  2048
#define MROWS (BTOT * SS)   // 100352 = 784 * 128
#define KDIM  512

// ---------------- scratch (__device__ globals; allocation-free rule) -------
__device__ __nv_bfloat16 g_xh[(size_t)MROWS * KDIM];
__device__ __nv_bfloat16 g_xl[(size_t)MROWS * KDIM];
__device__ float         g_qkv[(size_t)MROWS * 3 * DIM];
__device__ __nv_bfloat16 g_ah[(size_t)MROWS * DIM];
__device__ __nv_bfloat16 g_al[(size_t)MROWS * DIM];
__device__ __nv_bfloat16 g_wqh[(size_t)3 * DIM * KDIM];   // transposed [1536][512]
__device__ __nv_bfloat16 g_wql[(size_t)3 * DIM * KDIM];
__device__ __nv_bfloat16 g_wph[(size_t)DIM * KDIM];       // transposed [512][512]
__device__ __nv_bfloat16 g_wpl[(size_t)DIM * KDIM];
__device__ float         g_bm[4 * HEADS * SS * SS];       // bias+mask table

// ---------------- PTX helpers ---------------------------------------------
__device__ __forceinline__ uint32_t smem_u32(const void* p) {
    uint32_t a;
    asm("{ .reg .u64 t; cvta.to.shared.u64 t, %1; cvt.u32.u64 %0, t; }"
        : "=r"(a) : "l"(p));
    return a;
}
__device__ __forceinline__ void cpa16(uint32_t s, const void* g) {
    asm volatile("cp.async.cg.shared.global [%0], [%1], 16;" :: "r"(s), "l"(g));
}
#define CP_COMMIT() asm volatile("cp.async.commit_group;")
#define CP_WAIT1()  asm volatile("cp.async.wait_group 1;")
#define CP_WAIT0()  asm volatile("cp.async.wait_group 0;")

#define LDSM4(r, addr) \
    asm volatile("ldmatrix.sync.aligned.m8n8.x4.shared.b16 {%0,%1,%2,%3}, [%4];" \
        : "=r"((r)[0]), "=r"((r)[1]), "=r"((r)[2]), "=r"((r)[3]) : "r"(addr))

#define LDSM4T(r, addr) \
    asm volatile("ldmatrix.sync.aligned.m8n8.x4.trans.shared.b16 {%0,%1,%2,%3}, [%4];" \
        : "=r"((r)[0]), "=r"((r)[1]), "=r"((r)[2]), "=r"((r)[3]) : "r"(addr))

#define MMA16816(d, a, b0, b1) \
    asm volatile("mma.sync.aligned.m16n8k16.row.col.f32.bf16.bf16.f32 " \
        "{%0,%1,%2,%3}, {%4,%5,%6,%7}, {%8,%9}, {%0,%1,%2,%3};" \
        : "+f"((d)[0]), "+f"((d)[1]), "+f"((d)[2]), "+f"((d)[3]) \
        : "r"((a)[0]), "r"((a)[1]), "r"((a)[2]), "r"((a)[3]), "r"(b0), "r"(b1))

__device__ __forceinline__ uint32_t pack_bf162(__nv_bfloat16 a, __nv_bfloat16 b) {
    __nv_bfloat162 t(a, b);
    return *(uint32_t*)&t;
}

// ---------------------------------------------------------------------------
// Split-precision HMMA GEMM (R12-proven): C = (Ah+Al)@(Bh+Bl)^T + bias (fp32)
// Tile 128x128, BK=32, 3-stage cp.async pipeline, 64B swizzled rows,
// one sync/iter, loads 2 stages ahead. 2 CTAs/SM.
// ---------------------------------------------------------------------------
#define TSTRIDE     64
#define TILE_BYTES  (128 * TSTRIDE)          // 8192
#define STAGE_BYTES (4 * TILE_BYTES)         // 32768
#define GEMM_SMEM   (3 * STAGE_BYTES)        // 98304

__global__ __launch_bounds__(256, 2) void gemm_bf16x3_mma(
    const __nv_bfloat16* __restrict__ Ah, const __nv_bfloat16* __restrict__ Al,
    const __nv_bfloat16* __restrict__ Bh, const __nv_bfloat16* __restrict__ Bl,
    const float* __restrict__ bias, float* __restrict__ C, int N)
{
    extern __shared__ char smem[];
    const uint32_t sb = smem_u32(smem);
    const int tid  = threadIdx.x;
    const int lane = tid & 31, wid = tid >> 5;
    const int wr = wid >> 2, wc = wid & 3;
    const long m0 = (long)blockIdx.y * 128;
    const int  n0 = blockIdx.x * 128;

    auto load_stage = [&](int s, int k0) {
        const uint32_t base = sb + (uint32_t)s * STAGE_BYTES;
        #pragma unroll
        for (int half = 0; half < 2; half++) {
            const int chunk = tid + half * 256;
            const int r = chunk >> 2, c = chunk & 3;
            const int cs = c ^ ((r >> 1) & 3);
            const uint32_t off = (uint32_t)r * TSTRIDE + cs * 16;
            const long aIdx = (m0 + r) * (long)KDIM + k0 + c * 8;
            const long bIdx = ((long)n0 + r) * (long)KDIM + k0 + c * 8;
            cpa16(base + off,                  (const char*)(Ah + aIdx));
            cpa16(base + TILE_BYTES + off,     (const char*)(Al + aIdx));
            cpa16(base + 2 * TILE_BYTES + off, (const char*)(Bh + bIdx));
            cpa16(base + 3 * TILE_BYTES + off, (const char*)(Bl + bIdx));
        }
    };

    float acc[4][4][4];
    #pragma unroll
    for (int mi = 0; mi < 4; mi++)
        #pragma unroll
        for (int ni = 0; ni < 4; ni++)
            #pragma unroll
            for (int j = 0; j < 4; j++) acc[mi][ni][j] = 0.f;

    const int sA = ((lane & 15) >> 1) & 3;
    const int bg = lane >> 3, bfr = bg >> 1, bkh = bg & 1;
    const int sB = ((lane & 7) >> 1) & 3;
    const uint32_t cA[2] = { (uint32_t)(((lane >> 4) ^ sA) * 16),
                             (uint32_t)(((2 + (lane >> 4)) ^ sA) * 16) };
    const uint32_t cB[2] = { (uint32_t)((bkh ^ sB) * 16),
                             (uint32_t)(((2 + bkh) ^ sB) * 16) };
    const uint32_t aRowOff = (uint32_t)(wr * 64 + (lane & 15)) * TSTRIDE;
    const uint32_t bRowOff = 2 * TILE_BYTES +
        (uint32_t)(wc * 32 + bfr * 8 + (lane & 7)) * TSTRIDE;

    auto compute_stage = [&](int s) {
        const uint32_t base = sb + (uint32_t)s * STAGE_BYTES;
        #pragma unroll
        for (int kk = 0; kk < 2; kk++) {
            uint32_t bh[2][4], bl[2][4];
            #pragma unroll
            for (int p = 0; p < 2; p++) {
                uint32_t addr = base + bRowOff + (uint32_t)p * 16 * TSTRIDE + cB[kk];
                LDSM4(bh[p], addr);
                LDSM4(bl[p], addr + TILE_BYTES);
            }
            #pragma unroll
            for (int mi = 0; mi < 4; mi++) {
                uint32_t aaddr = base + aRowOff + (uint32_t)mi * 16 * TSTRIDE + cA[kk];
                uint32_t ah[4];
                LDSM4(ah, aaddr);
                #pragma unroll
                for (int p = 0; p < 2; p++)
                    #pragma unroll
                    for (int q2 = 0; q2 < 2; q2++) {
                        const int ni = p * 2 + q2, rb = q2 * 2;
                        MMA16816(acc[mi][ni], ah, bh[p][rb], bh[p][rb + 1]);
                        MMA16816(acc[mi][ni], ah, bl[p][rb], bl[p][rb + 1]);
                    }
                uint32_t al[4];
                LDSM4(al, aaddr + TILE_BYTES);
                #pragma unroll
                for (int p = 0; p < 2; p++)
                    #pragma unroll
                    for (int q2 = 0; q2 < 2; q2++) {
                        const int ni = p * 2 + q2, rb = q2 * 2;
                        MMA16816(acc[mi][ni], al, bh[p][rb], bh[p][rb + 1]);
                    }
            }
        }
    };

    load_stage(0, 0);  CP_COMMIT();
    load_stage(1, 32); CP_COMMIT();
    #pragma unroll 1
    for (int kt = 0; kt < 16; kt++) {
        if (kt < 15) { CP_WAIT1(); } else { CP_WAIT0(); }
        __syncthreads();
        if (kt + 2 < 16) {
            load_stage((kt + 2) % 3, (kt + 2) * 32);
            CP_COMMIT();
        }
        compute_stage(kt % 3);
    }

    const int r0 = lane >> 2, cpos = (lane & 3) * 2;
    #pragma unroll
    for (int ni = 0; ni < 4; ni++) {
        const int col = n0 + wc * 32 + ni * 8 + cpos;
        const float bx = bias[col], by = bias[col + 1];
        #pragma unroll
        for (int mi = 0; mi < 4; mi++) {
            const long row = m0 + wr * 64 + mi * 16 + r0;
            float2 v0 = {acc[mi][ni][0] + bx, acc[mi][ni][1] + by};
            float2 v1 = {acc[mi][ni][2] + bx, acc[mi][ni][3] + by};
            *(float2*)&C[row * (long)N + col]       = v0;
            *(float2*)&C[(row + 8) * (long)N + col] = v1;
        }
    }
}

// ---------------------------------------------------------------------------
// fp32 -> (hi, lo) bf16 split kernels
// ---------------------------------------------------------------------------
__global__ void split_kernel(const float* __restrict__ in,
                             __nv_bfloat16* __restrict__ hi,
                             __nv_bfloat16* __restrict__ lo, long n4)
{
    long i = (long)blockIdx.x * blockDim.x + threadIdx.x;
    const long stride = (long)gridDim.x * blockDim.x;
    for (; i < n4; i += stride) {
        float4 v = ((const float4*)in)[i];
        __nv_bfloat16 h0 = __float2bfloat16(v.x);
        __nv_bfloat16 h1 = __float2bfloat16(v.y);
        __nv_bfloat16 h2 = __float2bfloat16(v.z);
        __nv_bfloat16 h3 = __float2bfloat16(v.w);
        __nv_bfloat162* hp = (__nv_bfloat162*)hi + 2 * i;
        hp[0] = __nv_bfloat162(h0, h1);
        hp[1] = __nv_bfloat162(h2, h3);
        __nv_bfloat162* lp = (__nv_bfloat162*)lo + 2 * i;
        lp[0] = __nv_bfloat162(__float2bfloat16(v.x - __bfloat162float(h0)),
                               __float2bfloat16(v.y - __bfloat162float(h1)));
        lp[1] = __nv_bfloat162(__float2bfloat16(v.z - __bfloat162float(h2)),
                               __float2bfloat16(v.w - __bfloat162float(h3)));
    }
}

__global__ void wsplit_kernel(const float* __restrict__ w,
                              __nv_bfloat16* __restrict__ hi,
                              __nv_bfloat16* __restrict__ lo, int N, int total)
{
    int i = blockIdx.x * 256 + threadIdx.x;
    if (i >= total) return;
    int k = i & (KDIM - 1);
    int n = i >> 9;
    float v = w[(long)k * N + n];
    __nv_bfloat16 h = __float2bfloat16(v);
    hi[i] = h;
    lo[i] = __float2bfloat16(v - __bfloat162float(h));
}

__global__ void biasmask_kernel(const float* __restrict__ bias_table,
                                const int* __restrict__ rel_idx,
                                const float* __restrict__ mask,
                                float* __restrict__ bm)
{
    int idx = blockIdx.x * 256 + threadIdx.x;
    const int total = 4 * HEADS * SS * SS;
    if (idx >= total) return;
    int e = idx % (SS * SS);
    int h = (idx / (SS * SS)) % HEADS;
    int w = idx / (SS * SS * HEADS);
    bm[idx] = bias_table[rel_idx[e] * HEADS + h] + mask[w * SS * SS + e];
}

// ---------------------------------------------------------------------------
// MMA window attention (R12 base + FA2 register-P: the QK^T accumulator
// fragments ARE the P@V A-fragments — P never touches smem). 30720B smem.
// ---------------------------------------------------------------------------
#define AQH   0
#define AQL   5120
#define AKH   10240
#define AKL   15360
#define AVH   20480       // V hi, 64 rows x 80B
#define AVL   25600       // V lo
#define ATTN_SMEM 30720

__global__ __launch_bounds__(128) void attn_mma_kernel(
    const float* __restrict__ qkv, const float* __restrict__ bm_tab,
    __nv_bfloat16* __restrict__ out_hi, __nv_bfloat16* __restrict__ out_lo)
{
    extern __shared__ char smem[];
    const uint32_t sb = smem_u32(smem);
    const int b = blockIdx.x, h = blockIdx.y;
    const int tid = threadIdx.x, lane = tid & 31, w = tid >> 5;

    for (int i = tid; i < 300; i += 128) {          // q/k pad rows 49..63
        int r = 49 + i / 20, c = (i % 20) * 4;
        *(uint32_t*)(smem + AQH + r * 80 + c) = 0;
        *(uint32_t*)(smem + AQL + r * 80 + c) = 0;
        *(uint32_t*)(smem + AKH + r * 80 + c) = 0;
        *(uint32_t*)(smem + AKL + r * 80 + c) = 0;
    }
    for (int i = tid; i < 1280; i += 128) {         // whole V hi/lo
        *(uint32_t*)(smem + AVH + i * 4) = 0;
        *(uint32_t*)(smem + AVL + i * 4) = 0;
    }

    const float scale = 0.17677669529663687f;
    const float* base = qkv + (long)b * SS * (3 * DIM) + h * HD;
    for (int e = tid; e < 392; e += 128) {
        int s = e >> 3, d4 = (e & 7) * 4;
        const float* rp = base + (long)s * (3 * DIM) + d4;
        float4 qv = *(const float4*)rp;
        float4 kv = *(const float4*)(rp + DIM);
        float4 vv = *(const float4*)(rp + 2 * DIM);
        qv.x *= scale; qv.y *= scale; qv.z *= scale; qv.w *= scale;

        float qa[4] = {qv.x, qv.y, qv.z, qv.w};
        float ka[4] = {kv.x, kv.y, kv.z, kv.w};
        float va[4] = {vv.x, vv.y, vv.z, vv.w};
        __nv_bfloat16 qh_[4], ql_[4], kh_[4], kl_[4], vh_[4], vl_[4];
        #pragma unroll
        for (int j = 0; j < 4; j++) {
            qh_[j] = __float2bfloat16(qa[j]);
            ql_[j] = __float2bfloat16(qa[j] - __bfloat162float(qh_[j]));
            kh_[j] = __float2bfloat16(ka[j]);
            kl_[j] = __float2bfloat16(ka[j] - __bfloat162float(kh_[j]));
            vh_[j] = __float2bfloat16(va[j]);
            vl_[j] = __float2bfloat16(va[j] - __bfloat162float(vh_[j]));
        }
        uint32_t ro = (uint32_t)s * 80 + d4 * 2;
        *(__nv_bfloat162*)(smem + AQH + ro)     = __nv_bfloat162(qh_[0], qh_[1]);
        *(__nv_bfloat162*)(smem + AQH + ro + 4) = __nv_bfloat162(qh_[2], qh_[3]);
        *(__nv_bfloat162*)(smem + AQL + ro)     = __nv_bfloat162(ql_[0], ql_[1]);
        *(__nv_bfloat162*)(smem + AQL + ro + 4) = __nv_bfloat162(ql_[2], ql_[3]);
        *(__nv_bfloat162*)(smem + AKH + ro)     = __nv_bfloat162(kh_[0], kh_[1]);
        *(__nv_bfloat162*)(smem + AKH + ro + 4) = __nv_bfloat162(kh_[2], kh_[3]);
        *(__nv_bfloat162*)(smem + AKL + ro)     = __nv_bfloat162(kl_[0], kl_[1]);
        *(__nv_bfloat162*)(smem + AKL + ro + 4) = __nv_bfloat162(kl_[2], kl_[3]);
        *(__nv_bfloat162*)(smem + AVH + ro)     = __nv_bfloat162(vh_[0], vh_[1]);
        *(__nv_bfloat162*)(smem + AVH + ro + 4) = __nv_bfloat162(vh_[2], vh_[3]);
        *(__nv_bfloat162*)(smem + AVL + ro)     = __nv_bfloat162(vl_[0], vl_[1]);
        *(__nv_bfloat162*)(smem + AVL + ro + 4) = __nv_bfloat162(vl_[2], vl_[3]);
    }
    __syncthreads();

    float accs[8][4];
    #pragma unroll
    for (int ni = 0; ni < 8; ni++)
        #pragma unroll
        for (int j = 0; j < 4; j++) accs[ni][j] = 0.f;

    const uint32_t aQ = sb + AQH +
        (uint32_t)(w * 16 + (lane & 15)) * 80 + (lane >> 4) * 16;
    const int bg = lane >> 3, bfr = bg >> 1, bkh = bg & 1;
    const uint32_t bK = sb + AKH +
        (uint32_t)(bfr * 8 + (lane & 7)) * 80 + bkh * 16;

    #pragma unroll
    for (int kk = 0; kk < 2; kk++) {
        uint32_t ah[4], al[4];
        LDSM4(ah, aQ + kk * 32);
        LDSM4(al, aQ + (AQL - AQH) + kk * 32);
        #pragma unroll
        for (int p = 0; p < 4; p++) {
            uint32_t bh[4], bl[4];
            uint32_t addr = bK + (uint32_t)p * 16 * 80 + kk * 32;
            LDSM4(bh, addr);
            LDSM4(bl, addr + (AKL - AKH));
            #pragma unroll
            for (int q2 = 0; q2 < 2; q2++) {
                const int ni = p * 2 + q2, rb = q2 * 2;
                MMA16816(accs[ni], ah, bh[rb], bh[rb + 1]);
                MMA16816(accs[ni], ah, bl[rb], bl[rb + 1]);
                MMA16816(accs[ni], al, bh[rb], bh[rb + 1]);
            }
        }
    }

    const int r1 = lane >> 2, tq = lane & 3;
    const int row1 = w * 16 + r1, row2 = row1 + 8;
    {
        const float* bmr1 = bm_tab + ((long)(b & 3) * HEADS + h) * (SS * SS)
                            + (long)row1 * SS;
        const float* bmr2 = bmr1 + 8 * SS;
        const bool v1 = (row1 < SS), v2 = (row2 < SS);
        #pragma unroll
        for (int ni = 0; ni < 8; ni++) {
            const int c0 = ni * 8 + tq * 2, c1 = c0 + 1;
            if (c0 < SS) {
                if (v1) accs[ni][0] += bmr1[c0];
                if (v2) accs[ni][2] += bmr2[c0];
            } else { accs[ni][0] = -1e30f; accs[ni][2] = -1e30f; }
            if (c1 < SS) {
                if (v1) accs[ni][1] += bmr1[c1];
                if (v2) accs[ni][3] += bmr2[c1];
            } else { accs[ni][1] = -1e30f; accs[ni][3] = -1e30f; }
        }
        float m1 = -1e30f, m2 = -1e30f;
        #pragma unroll
        for (int ni = 0; ni < 8; ni++) {
            m1 = fmaxf(m1, fmaxf(accs[ni][0], accs[ni][1]));
            m2 = fmaxf(m2, fmaxf(accs[ni][2], accs[ni][3]));
        }
        m1 = fmaxf(m1, __shfl_xor_sync(0xffffffff, m1, 1));
        m1 = fmaxf(m1, __shfl_xor_sync(0xffffffff, m1, 2));
        m2 = fmaxf(m2, __shfl_xor_sync(0xffffffff, m2, 1));
        m2 = fmaxf(m2, __shfl_xor_sync(0xffffffff, m2, 2));
        float s1 = 0.f, s2 = 0.f;
        #pragma unroll
        for (int ni = 0; ni < 8; ni++) {
            accs[ni][0] = __expf(accs[ni][0] - m1);
            accs[ni][1] = __expf(accs[ni][1] - m1);
            accs[ni][2] = __expf(accs[ni][2] - m2);
            accs[ni][3] = __expf(accs[ni][3] - m2);
            s1 += accs[ni][0] + accs[ni][1];
            s2 += accs[ni][2] + accs[ni][3];
        }
        s1 += __shfl_xor_sync(0xffffffff, s1, 1);
        s1 += __shfl_xor_sync(0xffffffff, s1, 2);
        s2 += __shfl_xor_sync(0xffffffff, s2, 1);
        s2 += __shfl_xor_sync(0xffffffff, s2, 2);
        const float i1 = 1.0f / s1, i2 = 1.0f / s2;
        #pragma unroll
        for (int ni = 0; ni < 8; ni++) {
            accs[ni][0] *= i1; accs[ni][1] *= i1;
            accs[ni][2] *= i2; accs[ni][3] *= i2;
        }
    }
    // NO smem round-trip for P; accumulator fragments feed P@V directly.

    float acco[4][4];
    #pragma unroll
    for (int ni = 0; ni < 4; ni++)
        #pragma unroll
        for (int j = 0; j < 4; j++) acco[ni][j] = 0.f;

    const int vt = lane >> 3, vlr = lane & 7;
    const uint32_t bVt = sb + AVH +
        (uint32_t)((vt & 1) * 8 + vlr) * 80 + (vt >> 1) * 16;

    #pragma unroll
    for (int ks = 0; ks < 4; ks++) {
        // FA2: A-fragment for k-tile ks comes from acc tiles 2ks, 2ks+1.
        uint32_t ph_[4], pl_[4];
        #pragma unroll
        for (int half = 0; half < 2; half++) {
            const int ni = 2 * ks + half;
            float p0 = accs[ni][0], p1 = accs[ni][1];
            float p2 = accs[ni][2], p3 = accs[ni][3];
            __nv_bfloat16 h0 = __float2bfloat16(p0), h1 = __float2bfloat16(p1);
            __nv_bfloat16 h2 = __float2bfloat16(p2), h3 = __float2bfloat16(p3);
            ph_[half * 2 + 0] = pack_bf162(h0, h1);
            ph_[half * 2 + 1] = pack_bf162(h2, h3);
            pl_[half * 2 + 0] = pack_bf162(
                __float2bfloat16(p0 - __bfloat162float(h0)),
                __float2bfloat16(p1 - __bfloat162float(h1)));
            pl_[half * 2 + 1] = pack_bf162(
                __float2bfloat16(p2 - __bfloat162float(h2)),
                __float2bfloat16(p3 - __bfloat162float(h3)));
        }
        #pragma unroll
        for (int p = 0; p < 2; p++) {
            uint32_t bh[4], bl[4];
            uint32_t addr = bVt + (uint32_t)ks * (16 * 80) + p * 32;
            LDSM4T(bh, addr);
            LDSM4T(bl, addr + (AVL - AVH));
            #pragma unroll
            for (int q2 = 0; q2 < 2; q2++) {
                const int ni = p * 2 + q2, rb = q2 * 2;
                MMA16816(acco[ni], ph_, bh[rb], bh[rb + 1]);
                MMA16816(acco[ni], ph_, bl[rb], bl[rb + 1]);
                MMA16816(acco[ni], pl_, bh[rb], bh[rb + 1]);
            }
        }
    }

    #pragma unroll
    for (int ni = 0; ni < 4; ni++) {
        const int d0 = ni * 8 + tq * 2;
        if (row1 < SS) {
            long idx = ((long)b * SS + row1) * DIM + h * HD + d0;
            __nv_bfloat16 h0 = __float2bfloat16(acco[ni][0]);
            __nv_bfloat16 h1 = __float2bfloat16(acco[ni][1]);
            *(__nv_bfloat162*)(out_hi + idx) = __nv_bfloat162(h0, h1);
            *(__nv_bfloat162*)(out_lo + idx) = __nv_bfloat162(
                __float2bfloat16(acco[ni][0] - __bfloat162float(h0)),
                __float2bfloat16(acco[ni][1] - __bfloat162float(h1)));
        }
        if (row2 < SS) {
            long idx = ((long)b * SS + row2) * DIM + h * HD + d0;
            __nv_bfloat16 h2 = __float2bfloat16(acco[ni][2]);
            __nv_bfloat16 h3 = __float2bfloat16(acco[ni][3]);
            *(__nv_bfloat162*)(out_hi + idx) = __nv_bfloat162(h2, h3);
            *(__nv_bfloat162*)(out_lo + idx) = __nv_bfloat162(
                __float2bfloat16(acco[ni][2] - __bfloat162float(h2)),
                __float2bfloat16(acco[ni][3] - __bfloat162float(h3)));
        }
    }
}

// ---------------------------------------------------------------------------
extern "C" void kernel_launch(void* const* d_in, const int* in_sizes, int n_in,
                              void* d_out, int out_size)
{
    const float* x          = (const float*)d_in[0];
    const float* mask       = (const float*)d_in[1];
    const float* w_qkv      = (const float*)d_in[2];
    const float* b_qkv      = (const float*)d_in[3];
    const float* w_proj     = (const float*)d_in[4];
    const float* b_proj     = (const float*)d_in[5];
    const float* bias_table = (const float*)d_in[6];
    const int*   rel_idx    = (const int*)d_in[7];
    float* out = (float*)d_out;

    __nv_bfloat16 *xh, *xl, *ah, *al, *wqh, *wql, *wph, *wpl;
    float *qkv, *bm;
    cudaGetSymbolAddress((void**)&xh,  g_xh);
    cudaGetSymbolAddress((void**)&xl,  g_xl);
    cudaGetSymbolAddress((void**)&qkv, g_qkv);
    cudaGetSymbolAddress((void**)&ah,  g_ah);
    cudaGetSymbolAddress((void**)&al,  g_al);
    cudaGetSymbolAddress((void**)&wqh, g_wqh);
    cudaGetSymbolAddress((void**)&wql, g_wql);
    cudaGetSymbolAddress((void**)&wph, g_wph);
    cudaGetSymbolAddress((void**)&wpl, g_wpl);
    cudaGetSymbolAddress((void**)&bm,  g_bm);

    cudaFuncSetAttribute(gemm_bf16x3_mma,
                         cudaFuncAttributeMaxDynamicSharedMemorySize, GEMM_SMEM);
    cudaFuncSetAttribute(attn_mma_kernel,
                         cudaFuncAttributeMaxDynamicSharedMemorySize, ATTN_SMEM);

    // 1) splits + bias/mask table
    {
        long n4 = (long)MROWS * KDIM / 4;
        split_kernel<<<2048, 256>>>(x, xh, xl, n4);
        wsplit_kernel<<<(3 * DIM * KDIM) / 256, 256>>>(w_qkv, wqh, wql, 3 * DIM,
                                                       3 * DIM * KDIM);
        wsplit_kernel<<<(DIM * KDIM) / 256, 256>>>(w_proj, wph, wpl, DIM, DIM * KDIM);
        int bmtot = 4 * HEADS * SS * SS;
        biasmask_kernel<<<(bmtot + 255) / 256, 256>>>(bias_table, rel_idx, mask, bm);
    }

    // 2) QKV GEMM (fp32 out)
    {
        dim3 grid(12, 784);
        gemm_bf16x3_mma<<<grid, 256, GEMM_SMEM>>>(xh, xl, wqh, wql, b_qkv, qkv,
                                                  3 * DIM);
    }

    // 3) MMA window attention (register-P)
    {
        dim3 grid(BTOT, HEADS);
        attn_mma_kernel<<<grid, 128, ATTN_SMEM>>>(qkv, bm, ah, al);
    }

    // 4) Proj GEMM (fp32 out)
    {
        dim3 grid(4, 784);
        gemm_bf16x3_mma<<<grid, 256, GEMM_SMEM>>>(ah, al, wph, wpl, b_proj, out,
                                                  DIM);
    }
}

// round 15
// speedup vs baseline: 1.1739x; 1.0803x over previous
#include <cuda_runtime.h>
#include <cuda_bf16.h>
#include <cstdint>

#define DIM   512
#define HEADS 16
#define HD    32
#define SS    49
#define BTOT  2048
#define MROWS (BTOT * SS)   // 100352 = 784 * 128
#define KDIM  512

// ---------------- scratch (__device__ globals; allocation-free rule) -------
__device__ __nv_bfloat16 g_xh[(size_t)MROWS * KDIM];
__device__ __nv_bfloat16 g_xl[(size_t)MROWS * KDIM];
__device__ float         g_qkv[(size_t)MROWS * 3 * DIM];
__device__ __nv_bfloat16 g_ah[(size_t)MROWS * DIM];
__device__ __nv_bfloat16 g_al[(size_t)MROWS * DIM];
__device__ __nv_bfloat16 g_wqh[(size_t)3 * DIM * KDIM];   // transposed [1536][512]
__device__ __nv_bfloat16 g_wql[(size_t)3 * DIM * KDIM];
__device__ __nv_bfloat16 g_wph[(size_t)DIM * KDIM];       // transposed [512][512]
__device__ __nv_bfloat16 g_wpl[(size_t)DIM * KDIM];
__device__ float         g_bm[4 * HEADS * SS * SS];       // bias+mask table

// ---------------- PTX helpers ---------------------------------------------
__device__ __forceinline__ uint32_t smem_u32(const void* p) {
    uint32_t a;
    asm("{ .reg .u64 t; cvta.to.shared.u64 t, %1; cvt.u32.u64 %0, t; }"
        : "=r"(a) : "l"(p));
    return a;
}
__device__ __forceinline__ void cpa16(uint32_t s, const void* g) {
    asm volatile("cp.async.cg.shared.global [%0], [%1], 16;" :: "r"(s), "l"(g));
}
#define CP_COMMIT() asm volatile("cp.async.commit_group;")
#define CP_WAIT1()  asm volatile("cp.async.wait_group 1;")
#define CP_WAIT0()  asm volatile("cp.async.wait_group 0;")

#define LDSM4(r, addr) \
    asm volatile("ldmatrix.sync.aligned.m8n8.x4.shared.b16 {%0,%1,%2,%3}, [%4];" \
        : "=r"((r)[0]), "=r"((r)[1]), "=r"((r)[2]), "=r"((r)[3]) : "r"(addr))

#define LDSM4T(r, addr) \
    asm volatile("ldmatrix.sync.aligned.m8n8.x4.trans.shared.b16 {%0,%1,%2,%3}, [%4];" \
        : "=r"((r)[0]), "=r"((r)[1]), "=r"((r)[2]), "=r"((r)[3]) : "r"(addr))

#define MMA16816(d, a, b0, b1) \
    asm volatile("mma.sync.aligned.m16n8k16.row.col.f32.bf16.bf16.f32 " \
        "{%0,%1,%2,%3}, {%4,%5,%6,%7}, {%8,%9}, {%0,%1,%2,%3};" \
        : "+f"((d)[0]), "+f"((d)[1]), "+f"((d)[2]), "+f"((d)[3]) \
        : "r"((a)[0]), "r"((a)[1]), "r"((a)[2]), "r"((a)[3]), "r"(b0), "r"(b1))

__device__ __forceinline__ uint32_t pack_bf162(__nv_bfloat16 a, __nv_bfloat16 b) {
    __nv_bfloat162 t(a, b);
    return *(uint32_t*)&t;
}

// ---------------------------------------------------------------------------
// Split-precision HMMA GEMM: C = (Ah+Al)@(Bh+Bl)^T + bias (fp32)
// Tile 128x128, BK=32, 3-stage cp.async pipeline, 64B swizzled rows,
// one sync/iter; next-stage loads issued BETWEEN the two kk half-steps.
// ---------------------------------------------------------------------------
#define TSTRIDE     64
#define TILE_BYTES  (128 * TSTRIDE)          // 8192
#define STAGE_BYTES (4 * TILE_BYTES)         // 32768
#define GEMM_SMEM   (3 * STAGE_BYTES)        // 98304

__global__ __launch_bounds__(256, 2) void gemm_bf16x3_mma(
    const __nv_bfloat16* __restrict__ Ah, const __nv_bfloat16* __restrict__ Al,
    const __nv_bfloat16* __restrict__ Bh, const __nv_bfloat16* __restrict__ Bl,
    const float* __restrict__ bias, float* __restrict__ C, int N)
{
    extern __shared__ char smem[];
    const uint32_t sb = smem_u32(smem);
    const int tid  = threadIdx.x;
    const int lane = tid & 31, wid = tid >> 5;
    const int wr = wid >> 2, wc = wid & 3;
    const long m0 = (long)blockIdx.y * 128;
    const int  n0 = blockIdx.x * 128;

    auto load_stage = [&](int s, int k0) {
        const uint32_t base = sb + (uint32_t)s * STAGE_BYTES;
        #pragma unroll
        for (int half = 0; half < 2; half++) {
            const int chunk = tid + half * 256;
            const int r = chunk >> 2, c = chunk & 3;
            const int cs = c ^ ((r >> 1) & 3);
            const uint32_t off = (uint32_t)r * TSTRIDE + cs * 16;
            const long aIdx = (m0 + r) * (long)KDIM + k0 + c * 8;
            const long bIdx = ((long)n0 + r) * (long)KDIM + k0 + c * 8;
            cpa16(base + off,                  (const char*)(Ah + aIdx));
            cpa16(base + TILE_BYTES + off,     (const char*)(Al + aIdx));
            cpa16(base + 2 * TILE_BYTES + off, (const char*)(Bh + bIdx));
            cpa16(base + 3 * TILE_BYTES + off, (const char*)(Bl + bIdx));
        }
    };

    float acc[4][4][4];
    #pragma unroll
    for (int mi = 0; mi < 4; mi++)
        #pragma unroll
        for (int ni = 0; ni < 4; ni++)
            #pragma unroll
            for (int j = 0; j < 4; j++) acc[mi][ni][j] = 0.f;

    const int sA = ((lane & 15) >> 1) & 3;
    const int bg = lane >> 3, bfr = bg >> 1, bkh = bg & 1;
    const int sB = ((lane & 7) >> 1) & 3;
    const uint32_t cA[2] = { (uint32_t)(((lane >> 4) ^ sA) * 16),
                             (uint32_t)(((2 + (lane >> 4)) ^ sA) * 16) };
    const uint32_t cB[2] = { (uint32_t)((bkh ^ sB) * 16),
                             (uint32_t)(((2 + bkh) ^ sB) * 16) };
    const uint32_t aRowOff = (uint32_t)(wr * 64 + (lane & 15)) * TSTRIDE;
    const uint32_t bRowOff = 2 * TILE_BYTES +
        (uint32_t)(wc * 32 + bfr * 8 + (lane & 7)) * TSTRIDE;

    // one kk half-step (16 of the 32 K elements of a stage)
    auto compute_half = [&](int s, int kk) {
        const uint32_t base = sb + (uint32_t)s * STAGE_BYTES;
        uint32_t bh[2][4], bl[2][4];
        #pragma unroll
        for (int p = 0; p < 2; p++) {
            uint32_t addr = base + bRowOff + (uint32_t)p * 16 * TSTRIDE + cB[kk];
            LDSM4(bh[p], addr);
            LDSM4(bl[p], addr + TILE_BYTES);
        }
        #pragma unroll
        for (int mi = 0; mi < 4; mi++) {
            uint32_t aaddr = base + aRowOff + (uint32_t)mi * 16 * TSTRIDE + cA[kk];
            uint32_t ah[4];
            LDSM4(ah, aaddr);
            #pragma unroll
            for (int p = 0; p < 2; p++)
                #pragma unroll
                for (int q2 = 0; q2 < 2; q2++) {
                    const int ni = p * 2 + q2, rb = q2 * 2;
                    MMA16816(acc[mi][ni], ah, bh[p][rb], bh[p][rb + 1]);
                    MMA16816(acc[mi][ni], ah, bl[p][rb], bl[p][rb + 1]);
                }
            uint32_t al[4];
            LDSM4(al, aaddr + TILE_BYTES);
            #pragma unroll
            for (int p = 0; p < 2; p++)
                #pragma unroll
                for (int q2 = 0; q2 < 2; q2++) {
                    const int ni = p * 2 + q2, rb = q2 * 2;
                    MMA16816(acc[mi][ni], al, bh[p][rb], bh[p][rb + 1]);
                }
        }
    };

    // ---- 3-stage pipeline, 16 K-iters; loads issued between kk halves
    load_stage(0, 0);  CP_COMMIT();
    load_stage(1, 32); CP_COMMIT();
    #pragma unroll 1
    for (int kt = 0; kt < 16; kt++) {
        if (kt < 15) { CP_WAIT1(); } else { CP_WAIT0(); }
        __syncthreads();
        compute_half(kt % 3, 0);
        if (kt + 2 < 16) {
            load_stage((kt + 2) % 3, (kt + 2) * 32);
            CP_COMMIT();
        }
        compute_half(kt % 3, 1);
    }

    const int r0 = lane >> 2, cpos = (lane & 3) * 2;
    #pragma unroll
    for (int ni = 0; ni < 4; ni++) {
        const int col = n0 + wc * 32 + ni * 8 + cpos;
        const float bx = bias[col], by = bias[col + 1];
        #pragma unroll
        for (int mi = 0; mi < 4; mi++) {
            const long row = m0 + wr * 64 + mi * 16 + r0;
            float2 v0 = {acc[mi][ni][0] + bx, acc[mi][ni][1] + by};
            float2 v1 = {acc[mi][ni][2] + bx, acc[mi][ni][3] + by};
            *(float2*)&C[row * (long)N + col]       = v0;
            *(float2*)&C[(row + 8) * (long)N + col] = v1;
        }
    }
}

// ---------------------------------------------------------------------------
// fp32 -> (hi, lo) bf16 split kernels
// ---------------------------------------------------------------------------
__global__ void split_kernel(const float* __restrict__ in,
                             __nv_bfloat16* __restrict__ hi,
                             __nv_bfloat16* __restrict__ lo, long n4)
{
    long i = (long)blockIdx.x * blockDim.x + threadIdx.x;
    const long stride = (long)gridDim.x * blockDim.x;
    for (; i < n4; i += stride) {
        float4 v = ((const float4*)in)[i];
        __nv_bfloat16 h0 = __float2bfloat16(v.x);
        __nv_bfloat16 h1 = __float2bfloat16(v.y);
        __nv_bfloat16 h2 = __float2bfloat16(v.z);
        __nv_bfloat16 h3 = __float2bfloat16(v.w);
        __nv_bfloat162* hp = (__nv_bfloat162*)hi + 2 * i;
        hp[0] = __nv_bfloat162(h0, h1);
        hp[1] = __nv_bfloat162(h2, h3);
        __nv_bfloat162* lp = (__nv_bfloat162*)lo + 2 * i;
        lp[0] = __nv_bfloat162(__float2bfloat16(v.x - __bfloat162float(h0)),
                               __float2bfloat16(v.y - __bfloat162float(h1)));
        lp[1] = __nv_bfloat162(__float2bfloat16(v.z - __bfloat162float(h2)),
                               __float2bfloat16(v.w - __bfloat162float(h3)));
    }
}

__global__ void wsplit_kernel(const float* __restrict__ w,
                              __nv_bfloat16* __restrict__ hi,
                              __nv_bfloat16* __restrict__ lo, int N, int total)
{
    int i = blockIdx.x * 256 + threadIdx.x;
    if (i >= total) return;
    int k = i & (KDIM - 1);
    int n = i >> 9;
    float v = w[(long)k * N + n];
    __nv_bfloat16 h = __float2bfloat16(v);
    hi[i] = h;
    lo[i] = __float2bfloat16(v - __bfloat162float(h));
}

__global__ void biasmask_kernel(const float* __restrict__ bias_table,
                                const int* __restrict__ rel_idx,
                                const float* __restrict__ mask,
                                float* __restrict__ bm)
{
    int idx = blockIdx.x * 256 + threadIdx.x;
    const int total = 4 * HEADS * SS * SS;
    if (idx >= total) return;
    int e = idx % (SS * SS);
    int h = (idx / (SS * SS)) % HEADS;
    int w = idx / (SS * SS * HEADS);
    bm[idx] = bias_table[rel_idx[e] * HEADS + h] + mask[w * SS * SS + e];
}

// ---------------------------------------------------------------------------
// MMA window attention (R14: register-P FA2 style). 30720B smem, 4+ CTAs/SM.
// ---------------------------------------------------------------------------
#define AQH   0
#define AQL   5120
#define AKH   10240
#define AKL   15360
#define AVH   20480
#define AVL   25600
#define ATTN_SMEM 30720

__global__ __launch_bounds__(128) void attn_mma_kernel(
    const float* __restrict__ qkv, const float* __restrict__ bm_tab,
    __nv_bfloat16* __restrict__ out_hi, __nv_bfloat16* __restrict__ out_lo)
{
    extern __shared__ char smem[];
    const uint32_t sb = smem_u32(smem);
    const int b = blockIdx.x, h = blockIdx.y;
    const int tid = threadIdx.x, lane = tid & 31, w = tid >> 5;

    for (int i = tid; i < 300; i += 128) {
        int r = 49 + i / 20, c = (i % 20) * 4;
        *(uint32_t*)(smem + AQH + r * 80 + c) = 0;
        *(uint32_t*)(smem + AQL + r * 80 + c) = 0;
        *(uint32_t*)(smem + AKH + r * 80 + c) = 0;
        *(uint32_t*)(smem + AKL + r * 80 + c) = 0;
    }
    for (int i = tid; i < 1280; i += 128) {
        *(uint32_t*)(smem + AVH + i * 4) = 0;
        *(uint32_t*)(smem + AVL + i * 4) = 0;
    }

    const float scale = 0.17677669529663687f;
    const float* base = qkv + (long)b * SS * (3 * DIM) + h * HD;
    for (int e = tid; e < 392; e += 128) {
        int s = e >> 3, d4 = (e & 7) * 4;
        const float* rp = base + (long)s * (3 * DIM) + d4;
        float4 qv = *(const float4*)rp;
        float4 kv = *(const float4*)(rp + DIM);
        float4 vv = *(const float4*)(rp + 2 * DIM);
        qv.x *= scale; qv.y *= scale; qv.z *= scale; qv.w *= scale;

        float qa[4] = {qv.x, qv.y, qv.z, qv.w};
        float ka[4] = {kv.x, kv.y, kv.z, kv.w};
        float va[4] = {vv.x, vv.y, vv.z, vv.w};
        __nv_bfloat16 qh_[4], ql_[4], kh_[4], kl_[4], vh_[4], vl_[4];
        #pragma unroll
        for (int j = 0; j < 4; j++) {
            qh_[j] = __float2bfloat16(qa[j]);
            ql_[j] = __float2bfloat16(qa[j] - __bfloat162float(qh_[j]));
            kh_[j] = __float2bfloat16(ka[j]);
            kl_[j] = __float2bfloat16(ka[j] - __bfloat162float(kh_[j]));
            vh_[j] = __float2bfloat16(va[j]);
            vl_[j] = __float2bfloat16(va[j] - __bfloat162float(vh_[j]));
        }
        uint32_t ro = (uint32_t)s * 80 + d4 * 2;
        *(__nv_bfloat162*)(smem + AQH + ro)     = __nv_bfloat162(qh_[0], qh_[1]);
        *(__nv_bfloat162*)(smem + AQH + ro + 4) = __nv_bfloat162(qh_[2], qh_[3]);
        *(__nv_bfloat162*)(smem + AQL + ro)     = __nv_bfloat162(ql_[0], ql_[1]);
        *(__nv_bfloat162*)(smem + AQL + ro + 4) = __nv_bfloat162(ql_[2], ql_[3]);
        *(__nv_bfloat162*)(smem + AKH + ro)     = __nv_bfloat162(kh_[0], kh_[1]);
        *(__nv_bfloat162*)(smem + AKH + ro + 4) = __nv_bfloat162(kh_[2], kh_[3]);
        *(__nv_bfloat162*)(smem + AKL + ro)     = __nv_bfloat162(kl_[0], kl_[1]);
        *(__nv_bfloat162*)(smem + AKL + ro + 4) = __nv_bfloat162(kl_[2], kl_[3]);
        *(__nv_bfloat162*)(smem + AVH + ro)     = __nv_bfloat162(vh_[0], vh_[1]);
        *(__nv_bfloat162*)(smem + AVH + ro + 4) = __nv_bfloat162(vh_[2], vh_[3]);
        *(__nv_bfloat162*)(smem + AVL + ro)     = __nv_bfloat162(vl_[0], vl_[1]);
        *(__nv_bfloat162*)(smem + AVL + ro + 4) = __nv_bfloat162(vl_[2], vl_[3]);
    }
    __syncthreads();

    float accs[8][4];
    #pragma unroll
    for (int ni = 0; ni < 8; ni++)
        #pragma unroll
        for (int j = 0; j < 4; j++) accs[ni][j] = 0.f;

    const uint32_t aQ = sb + AQH +
        (uint32_t)(w * 16 + (lane & 15)) * 80 + (lane >> 4) * 16;
    const int bg = lane >> 3, bfr = bg >> 1, bkh = bg & 1;
    const uint32_t bK = sb + AKH +
        (uint32_t)(bfr * 8 + (lane & 7)) * 80 + bkh * 16;

    #pragma unroll
    for (int kk = 0; kk < 2; kk++) {
        uint32_t ah[4], al[4];
        LDSM4(ah, aQ + kk * 32);
        LDSM4(al, aQ + (AQL - AQH) + kk * 32);
        #pragma unroll
        for (int p = 0; p < 4; p++) {
            uint32_t bh[4], bl[4];
            uint32_t addr = bK + (uint32_t)p * 16 * 80 + kk * 32;
            LDSM4(bh, addr);
            LDSM4(bl, addr + (AKL - AKH));
            #pragma unroll
            for (int q2 = 0; q2 < 2; q2++) {
                const int ni = p * 2 + q2, rb = q2 * 2;
                MMA16816(accs[ni], ah, bh[rb], bh[rb + 1]);
                MMA16816(accs[ni], ah, bl[rb], bl[rb + 1]);
                MMA16816(accs[ni], al, bh[rb], bh[rb + 1]);
            }
        }
    }

    const int r1 = lane >> 2, tq = lane & 3;
    const int row1 = w * 16 + r1, row2 = row1 + 8;
    {
        const float* bmr1 = bm_tab + ((long)(b & 3) * HEADS + h) * (SS * SS)
                            + (long)row1 * SS;
        const float* bmr2 = bmr1 + 8 * SS;
        const bool v1 = (row1 < SS), v2 = (row2 < SS);
        #pragma unroll
        for (int ni = 0; ni < 8; ni++) {
            const int c0 = ni * 8 + tq * 2, c1 = c0 + 1;
            if (c0 < SS) {
                if (v1) accs[ni][0] += bmr1[c0];
                if (v2) accs[ni][2] += bmr2[c0];
            } else { accs[ni][0] = -1e30f; accs[ni][2] = -1e30f; }
            if (c1 < SS) {
                if (v1) accs[ni][1] += bmr1[c1];
                if (v2) accs[ni][3] += bmr2[c1];
            } else { accs[ni][1] = -1e30f; accs[ni][3] = -1e30f; }
        }
        float m1 = -1e30f, m2 = -1e30f;
        #pragma unroll
        for (int ni = 0; ni < 8; ni++) {
            m1 = fmaxf(m1, fmaxf(accs[ni][0], accs[ni][1]));
            m2 = fmaxf(m2, fmaxf(accs[ni][2], accs[ni][3]));
        }
        m1 = fmaxf(m1, __shfl_xor_sync(0xffffffff, m1, 1));
        m1 = fmaxf(m1, __shfl_xor_sync(0xffffffff, m1, 2));
        m2 = fmaxf(m2, __shfl_xor_sync(0xffffffff, m2, 1));
        m2 = fmaxf(m2, __shfl_xor_sync(0xffffffff, m2, 2));
        float s1 = 0.f, s2 = 0.f;
        #pragma unroll
        for (int ni = 0; ni < 8; ni++) {
            accs[ni][0] = __expf(accs[ni][0] - m1);
            accs[ni][1] = __expf(accs[ni][1] - m1);
            accs[ni][2] = __expf(accs[ni][2] - m2);
            accs[ni][3] = __expf(accs[ni][3] - m2);
            s1 += accs[ni][0] + accs[ni][1];
            s2 += accs[ni][2] + accs[ni][3];
        }
        s1 += __shfl_xor_sync(0xffffffff, s1, 1);
        s1 += __shfl_xor_sync(0xffffffff, s1, 2);
        s2 += __shfl_xor_sync(0xffffffff, s2, 1);
        s2 += __shfl_xor_sync(0xffffffff, s2, 2);
        const float i1 = 1.0f / s1, i2 = 1.0f / s2;
        #pragma unroll
        for (int ni = 0; ni < 8; ni++) {
            accs[ni][0] *= i1; accs[ni][1] *= i1;
            accs[ni][2] *= i2; accs[ni][3] *= i2;
        }
    }

    float acco[4][4];
    #pragma unroll
    for (int ni = 0; ni < 4; ni++)
        #pragma unroll
        for (int j = 0; j < 4; j++) acco[ni][j] = 0.f;

    const int vt = lane >> 3, vlr = lane & 7;
    const uint32_t bVt = sb + AVH +
        (uint32_t)((vt & 1) * 8 + vlr) * 80 + (vt >> 1) * 16;

    #pragma unroll
    for (int ks = 0; ks < 4; ks++) {
        uint32_t ph_[4], pl_[4];
        #pragma unroll
        for (int half = 0; half < 2; half++) {
            const int ni = 2 * ks + half;
            float p0 = accs[ni][0], p1 = accs[ni][1];
            float p2 = accs[ni][2], p3 = accs[ni][3];
            __nv_bfloat16 h0 = __float2bfloat16(p0), h1 = __float2bfloat16(p1);
            __nv_bfloat16 h2 = __float2bfloat16(p2), h3 = __float2bfloat16(p3);
            ph_[half * 2 + 0] = pack_bf162(h0, h1);
            ph_[half * 2 + 1] = pack_bf162(h2, h3);
            pl_[half * 2 + 0] = pack_bf162(
                __float2bfloat16(p0 - __bfloat162float(h0)),
                __float2bfloat16(p1 - __bfloat162float(h1)));
            pl_[half * 2 + 1] = pack_bf162(
                __float2bfloat16(p2 - __bfloat162float(h2)),
                __float2bfloat16(p3 - __bfloat162float(h3)));
        }
        #pragma unroll
        for (int p = 0; p < 2; p++) {
            uint32_t bh[4], bl[4];
            uint32_t addr = bVt + (uint32_t)ks * (16 * 80) + p * 32;
            LDSM4T(bh, addr);
            LDSM4T(bl, addr + (AVL - AVH));
            #pragma unroll
            for (int q2 = 0; q2 < 2; q2++) {
                const int ni = p * 2 + q2, rb = q2 * 2;
                MMA16816(acco[ni], ph_, bh[rb], bh[rb + 1]);
                MMA16816(acco[ni], ph_, bl[rb], bl[rb + 1]);
                MMA16816(acco[ni], pl_, bh[rb], bh[rb + 1]);
            }
        }
    }

    #pragma unroll
    for (int ni = 0; ni < 4; ni++) {
        const int d0 = ni * 8 + tq * 2;
        if (row1 < SS) {
            long idx = ((long)b * SS + row1) * DIM + h * HD + d0;
            __nv_bfloat16 h0 = __float2bfloat16(acco[ni][0]);
            __nv_bfloat16 h1 = __float2bfloat16(acco[ni][1]);
            *(__nv_bfloat162*)(out_hi + idx) = __nv_bfloat162(h0, h1);
            *(__nv_bfloat162*)(out_lo + idx) = __nv_bfloat162(
                __float2bfloat16(acco[ni][0] - __bfloat162float(h0)),
                __float2bfloat16(acco[ni][1] - __bfloat162float(h1)));
        }
        if (row2 < SS) {
            long idx = ((long)b * SS + row2) * DIM + h * HD + d0;
            __nv_bfloat16 h2 = __float2bfloat16(acco[ni][2]);
            __nv_bfloat16 h3 = __float2bfloat16(acco[ni][3]);
            *(__nv_bfloat162*)(out_hi + idx) = __nv_bfloat162(h2, h3);
            *(__nv_bfloat162*)(out_lo + idx) = __nv_bfloat162(
                __float2bfloat16(acco[ni][2] - __bfloat162float(h2)),
                __float2bfloat16(acco[ni][3] - __bfloat162float(h3)));
        }
    }
}

// ---------------------------------------------------------------------------
extern "C" void kernel_launch(void* const* d_in, const int* in_sizes, int n_in,
                              void* d_out, int out_size)
{
    const float* x          = (const float*)d_in[0];
    const float* mask       = (const float*)d_in[1];
    const float* w_qkv      = (const float*)d_in[2];
    const float* b_qkv      = (const float*)d_in[3];
    const float* w_proj     = (const float*)d_in[4];
    const float* b_proj     = (const float*)d_in[5];
    const float* bias_table = (const float*)d_in[6];
    const int*   rel_idx    = (const int*)d_in[7];
    float* out = (float*)d_out;

    __nv_bfloat16 *xh, *xl, *ah, *al, *wqh, *wql, *wph, *wpl;
    float *qkv, *bm;
    cudaGetSymbolAddress((void**)&xh,  g_xh);
    cudaGetSymbolAddress((void**)&xl,  g_xl);
    cudaGetSymbolAddress((void**)&qkv, g_qkv);
    cudaGetSymbolAddress((void**)&ah,  g_ah);
    cudaGetSymbolAddress((void**)&al,  g_al);
    cudaGetSymbolAddress((void**)&wqh, g_wqh);
    cudaGetSymbolAddress((void**)&wql, g_wql);
    cudaGetSymbolAddress((void**)&wph, g_wph);
    cudaGetSymbolAddress((void**)&wpl, g_wpl);
    cudaGetSymbolAddress((void**)&bm,  g_bm);

    cudaFuncSetAttribute(gemm_bf16x3_mma,
                         cudaFuncAttributeMaxDynamicSharedMemorySize, GEMM_SMEM);
    cudaFuncSetAttribute(attn_mma_kernel,
                         cudaFuncAttributeMaxDynamicSharedMemorySize, ATTN_SMEM);

    // 1) input/weight splits (launches 1-3)
    {
        long n4 = (long)MROWS * KDIM / 4;
        split_kernel<<<2048, 256>>>(x, xh, xl, n4);
        wsplit_kernel<<<(3 * DIM * KDIM) / 256, 256>>>(w_qkv, wqh, wql, 3 * DIM,
                                                       3 * DIM * KDIM);
        wsplit_kernel<<<(DIM * KDIM) / 256, 256>>>(w_proj, wph, wpl, DIM, DIM * KDIM);
    }

    // 2) QKV GEMM — launch #4 (lands on the ncu capture slot)
    {
        dim3 grid(12, 784);
        gemm_bf16x3_mma<<<grid, 256, GEMM_SMEM>>>(xh, xl, wqh, wql, b_qkv, qkv,
                                                  3 * DIM);
    }

    // 3) bias+mask table (only needed by attention; moved after the GEMM)
    {
        int bmtot = 4 * HEADS * SS * SS;
        biasmask_kernel<<<(bmtot + 255) / 256, 256>>>(bias_table, rel_idx, mask, bm);
    }

    // 4) MMA window attention (register-P)
    {
        dim3 grid(BTOT, HEADS);
        attn_mma_kernel<<<grid, 128, ATTN_SMEM>>>(qkv, bm, ah, al);
    }

    // 5) Proj GEMM (fp32 out)
    {
        dim3 grid(4, 784);
        gemm_bf16x3_mma<<<grid, 256, GEMM_SMEM>>>(ah, al, wph, wpl, b_proj, out,
                                                  DIM);
    }
}

// round 16
// speedup vs baseline: 1.1790x; 1.0044x over previous
#include <cuda_runtime.h>
#include <cuda_bf16.h>
#include <cstdint>

#define DIM   512
#define HEADS 16
#define HD    32
#define SS    49
#define BTOT  2048
#define MROWS (BTOT * SS)   // 100352 = 784 * 128
#define KDIM  512

// ---------------- scratch (__device__ globals; allocation-free rule) -------
__device__ __nv_bfloat16 g_xh[(size_t)MROWS * KDIM];
__device__ __nv_bfloat16 g_xl[(size_t)MROWS * KDIM];
__device__ float         g_qkv[(size_t)MROWS * 3 * DIM];
__device__ __nv_bfloat16 g_ah[(size_t)MROWS * DIM];
__device__ __nv_bfloat16 g_al[(size_t)MROWS * DIM];
__device__ __nv_bfloat16 g_wqh[(size_t)3 * DIM * KDIM];   // transposed [1536][512]
__device__ __nv_bfloat16 g_wql[(size_t)3 * DIM * KDIM];
__device__ __nv_bfloat16 g_wph[(size_t)DIM * KDIM];       // transposed [512][512]
__device__ __nv_bfloat16 g_wpl[(size_t)DIM * KDIM];
__device__ float         g_bm[4 * HEADS * 64 * 64];       // PADDED bias+mask

// ---------------- PTX helpers ---------------------------------------------
__device__ __forceinline__ uint32_t smem_u32(const void* p) {
    uint32_t a;
    asm("{ .reg .u64 t; cvta.to.shared.u64 t, %1; cvt.u32.u64 %0, t; }"
        : "=r"(a) : "l"(p));
    return a;
}
__device__ __forceinline__ void cpa16(uint32_t s, const void* g) {
    asm volatile("cp.async.cg.shared.global [%0], [%1], 16;" :: "r"(s), "l"(g));
}
#define CP_COMMIT() asm volatile("cp.async.commit_group;")
#define CP_WAIT1()  asm volatile("cp.async.wait_group 1;")
#define CP_WAIT0()  asm volatile("cp.async.wait_group 0;")

#define LDSM4(r, addr) \
    asm volatile("ldmatrix.sync.aligned.m8n8.x4.shared.b16 {%0,%1,%2,%3}, [%4];" \
        : "=r"((r)[0]), "=r"((r)[1]), "=r"((r)[2]), "=r"((r)[3]) : "r"(addr))

#define LDSM4T(r, addr) \
    asm volatile("ldmatrix.sync.aligned.m8n8.x4.trans.shared.b16 {%0,%1,%2,%3}, [%4];" \
        : "=r"((r)[0]), "=r"((r)[1]), "=r"((r)[2]), "=r"((r)[3]) : "r"(addr))

#define MMA16816(d, a, b0, b1) \
    asm volatile("mma.sync.aligned.m16n8k16.row.col.f32.bf16.bf16.f32 " \
        "{%0,%1,%2,%3}, {%4,%5,%6,%7}, {%8,%9}, {%0,%1,%2,%3};" \
        : "+f"((d)[0]), "+f"((d)[1]), "+f"((d)[2]), "+f"((d)[3]) \
        : "r"((a)[0]), "r"((a)[1]), "r"((a)[2]), "r"((a)[3]), "r"(b0), "r"(b1))

__device__ __forceinline__ uint32_t pack_bf162(__nv_bfloat16 a, __nv_bfloat16 b) {
    __nv_bfloat162 t(a, b);
    return *(uint32_t*)&t;
}

// ---------------------------------------------------------------------------
// Split-precision HMMA GEMM: C = (Ah+Al)@(Bh+Bl)^T + bias (fp32)
// Tile 128x128, BK=32, 3-stage cp.async pipeline, 64B swizzled rows,
// one sync/iter; next-stage loads issued BETWEEN the two kk half-steps.
// Stage indices via increment-wrap counters (no %3 in the loop).
// ---------------------------------------------------------------------------
#define TSTRIDE     64
#define TILE_BYTES  (128 * TSTRIDE)          // 8192
#define STAGE_BYTES (4 * TILE_BYTES)         // 32768
#define GEMM_SMEM   (3 * STAGE_BYTES)        // 98304

__global__ __launch_bounds__(256, 2) void gemm_bf16x3_mma(
    const __nv_bfloat16* __restrict__ Ah, const __nv_bfloat16* __restrict__ Al,
    const __nv_bfloat16* __restrict__ Bh, const __nv_bfloat16* __restrict__ Bl,
    const float* __restrict__ bias, float* __restrict__ C, int N)
{
    extern __shared__ char smem[];
    const uint32_t sb = smem_u32(smem);
    const int tid  = threadIdx.x;
    const int lane = tid & 31, wid = tid >> 5;
    const int wr = wid >> 2, wc = wid & 3;
    const long m0 = (long)blockIdx.y * 128;
    const int  n0 = blockIdx.x * 128;

    auto load_stage = [&](int s, int k0) {
        const uint32_t base = sb + (uint32_t)s * STAGE_BYTES;
        #pragma unroll
        for (int half = 0; half < 2; half++) {
            const int chunk = tid + half * 256;
            const int r = chunk >> 2, c = chunk & 3;
            const int cs = c ^ ((r >> 1) & 3);
            const uint32_t off = (uint32_t)r * TSTRIDE + cs * 16;
            const long aIdx = (m0 + r) * (long)KDIM + k0 + c * 8;
            const long bIdx = ((long)n0 + r) * (long)KDIM + k0 + c * 8;
            cpa16(base + off,                  (const char*)(Ah + aIdx));
            cpa16(base + TILE_BYTES + off,     (const char*)(Al + aIdx));
            cpa16(base + 2 * TILE_BYTES + off, (const char*)(Bh + bIdx));
            cpa16(base + 3 * TILE_BYTES + off, (const char*)(Bl + bIdx));
        }
    };

    float acc[4][4][4];
    #pragma unroll
    for (int mi = 0; mi < 4; mi++)
        #pragma unroll
        for (int ni = 0; ni < 4; ni++)
            #pragma unroll
            for (int j = 0; j < 4; j++) acc[mi][ni][j] = 0.f;

    const int sA = ((lane & 15) >> 1) & 3;
    const int bg = lane >> 3, bfr = bg >> 1, bkh = bg & 1;
    const int sB = ((lane & 7) >> 1) & 3;
    const uint32_t cA[2] = { (uint32_t)(((lane >> 4) ^ sA) * 16),
                             (uint32_t)(((2 + (lane >> 4)) ^ sA) * 16) };
    const uint32_t cB[2] = { (uint32_t)((bkh ^ sB) * 16),
                             (uint32_t)(((2 + bkh) ^ sB) * 16) };
    const uint32_t aRowOff = (uint32_t)(wr * 64 + (lane & 15)) * TSTRIDE;
    const uint32_t bRowOff = 2 * TILE_BYTES +
        (uint32_t)(wc * 32 + bfr * 8 + (lane & 7)) * TSTRIDE;

    auto compute_half = [&](int s, int kk) {
        const uint32_t base = sb + (uint32_t)s * STAGE_BYTES;
        uint32_t bh[2][4], bl[2][4];
        #pragma unroll
        for (int p = 0; p < 2; p++) {
            uint32_t addr = base + bRowOff + (uint32_t)p * 16 * TSTRIDE + cB[kk];
            LDSM4(bh[p], addr);
            LDSM4(bl[p], addr + TILE_BYTES);
        }
        #pragma unroll
        for (int mi = 0; mi < 4; mi++) {
            uint32_t aaddr = base + aRowOff + (uint32_t)mi * 16 * TSTRIDE + cA[kk];
            uint32_t ah[4];
            LDSM4(ah, aaddr);
            #pragma unroll
            for (int p = 0; p < 2; p++)
                #pragma unroll
                for (int q2 = 0; q2 < 2; q2++) {
                    const int ni = p * 2 + q2, rb = q2 * 2;
                    MMA16816(acc[mi][ni], ah, bh[p][rb], bh[p][rb + 1]);
                    MMA16816(acc[mi][ni], ah, bl[p][rb], bl[p][rb + 1]);
                }
            uint32_t al[4];
            LDSM4(al, aaddr + TILE_BYTES);
            #pragma unroll
            for (int p = 0; p < 2; p++)
                #pragma unroll
                for (int q2 = 0; q2 < 2; q2++) {
                    const int ni = p * 2 + q2, rb = q2 * 2;
                    MMA16816(acc[mi][ni], al, bh[p][rb], bh[p][rb + 1]);
                }
        }
    };

    // ---- 3-stage pipeline, 16 K-iters; loads issued between kk halves
    load_stage(0, 0);  CP_COMMIT();
    load_stage(1, 32); CP_COMMIT();
    int sCur = 0, sNext = 2;         // wrap counters (no %3)
    #pragma unroll 1
    for (int kt = 0; kt < 16; kt++) {
        if (kt < 15) { CP_WAIT1(); } else { CP_WAIT0(); }
        __syncthreads();
        compute_half(sCur, 0);
        if (kt + 2 < 16) {
            load_stage(sNext, (kt + 2) * 32);
            CP_COMMIT();
        }
        compute_half(sCur, 1);
        sCur  = (sCur == 2)  ? 0 : sCur + 1;
        sNext = (sNext == 2) ? 0 : sNext + 1;
    }

    const int r0 = lane >> 2, cpos = (lane & 3) * 2;
    #pragma unroll
    for (int ni = 0; ni < 4; ni++) {
        const int col = n0 + wc * 32 + ni * 8 + cpos;
        const float bx = bias[col], by = bias[col + 1];
        #pragma unroll
        for (int mi = 0; mi < 4; mi++) {
            const long row = m0 + wr * 64 + mi * 16 + r0;
            float2 v0 = {acc[mi][ni][0] + bx, acc[mi][ni][1] + by};
            float2 v1 = {acc[mi][ni][2] + bx, acc[mi][ni][3] + by};
            *(float2*)&C[row * (long)N + col]       = v0;
            *(float2*)&C[(row + 8) * (long)N + col] = v1;
        }
    }
}

// ---------------------------------------------------------------------------
// fp32 -> (hi, lo) bf16 split kernels
// ---------------------------------------------------------------------------
__global__ void split_kernel(const float* __restrict__ in,
                             __nv_bfloat16* __restrict__ hi,
                             __nv_bfloat16* __restrict__ lo, long n4)
{
    long i = (long)blockIdx.x * blockDim.x + threadIdx.x;
    const long stride = (long)gridDim.x * blockDim.x;
    for (; i < n4; i += stride) {
        float4 v = ((const float4*)in)[i];
        __nv_bfloat16 h0 = __float2bfloat16(v.x);
        __nv_bfloat16 h1 = __float2bfloat16(v.y);
        __nv_bfloat16 h2 = __float2bfloat16(v.z);
        __nv_bfloat16 h3 = __float2bfloat16(v.w);
        __nv_bfloat162* hp = (__nv_bfloat162*)hi + 2 * i;
        hp[0] = __nv_bfloat162(h0, h1);
        hp[1] = __nv_bfloat162(h2, h3);
        __nv_bfloat162* lp = (__nv_bfloat162*)lo + 2 * i;
        lp[0] = __nv_bfloat162(__float2bfloat16(v.x - __bfloat162float(h0)),
                               __float2bfloat16(v.y - __bfloat162float(h1)));
        lp[1] = __nv_bfloat162(__float2bfloat16(v.z - __bfloat162float(h2)),
                               __float2bfloat16(v.w - __bfloat162float(h3)));
    }
}

__global__ void wsplit_kernel(const float* __restrict__ w,
                              __nv_bfloat16* __restrict__ hi,
                              __nv_bfloat16* __restrict__ lo, int N, int total)
{
    int i = blockIdx.x * 256 + threadIdx.x;
    if (i >= total) return;
    int k = i & (KDIM - 1);
    int n = i >> 9;
    float v = w[(long)k * N + n];
    __nv_bfloat16 h = __float2bfloat16(v);
    hi[i] = h;
    lo[i] = __float2bfloat16(v - __bfloat162float(h));
}

// PADDED bias+mask table [4][16][64][64]; pads = -1e30
__global__ void biasmask_kernel(const float* __restrict__ bias_table,
                                const int* __restrict__ rel_idx,
                                const float* __restrict__ mask,
                                float* __restrict__ bm)
{
    int idx = blockIdx.x * 256 + threadIdx.x;
    const int total = 4 * HEADS * 64 * 64;
    if (idx >= total) return;
    int c = idx & 63;
    int r = (idx >> 6) & 63;
    int h = (idx >> 12) & (HEADS - 1);
    int w = idx >> 16;
    float val = -1e30f;
    if (r < SS && c < SS)
        val = bias_table[rel_idx[r * SS + c] * HEADS + h] + mask[w * SS * SS + r * SS + c];
    bm[idx] = val;
}

// ---------------------------------------------------------------------------
// MMA window attention (register-P). Padded bm table -> unconditional
// vectorized bias adds, no guards. 30720B smem.
// ---------------------------------------------------------------------------
#define AQH   0
#define AQL   5120
#define AKH   10240
#define AKL   15360
#define AVH   20480
#define AVL   25600
#define ATTN_SMEM 30720

__global__ __launch_bounds__(128) void attn_mma_kernel(
    const float* __restrict__ qkv, const float* __restrict__ bm_tab,
    __nv_bfloat16* __restrict__ out_hi, __nv_bfloat16* __restrict__ out_lo)
{
    extern __shared__ char smem[];
    const uint32_t sb = smem_u32(smem);
    const int b = blockIdx.x, h = blockIdx.y;
    const int tid = threadIdx.x, lane = tid & 31, w = tid >> 5;

    for (int i = tid; i < 300; i += 128) {
        int r = 49 + i / 20, c = (i % 20) * 4;
        *(uint32_t*)(smem + AQH + r * 80 + c) = 0;
        *(uint32_t*)(smem + AQL + r * 80 + c) = 0;
        *(uint32_t*)(smem + AKH + r * 80 + c) = 0;
        *(uint32_t*)(smem + AKL + r * 80 + c) = 0;
    }
    for (int i = tid; i < 1280; i += 128) {
        *(uint32_t*)(smem + AVH + i * 4) = 0;
        *(uint32_t*)(smem + AVL + i * 4) = 0;
    }

    const float scale = 0.17677669529663687f;
    const float* base = qkv + (long)b * SS * (3 * DIM) + h * HD;
    for (int e = tid; e < 392; e += 128) {
        int s = e >> 3, d4 = (e & 7) * 4;
        const float* rp = base + (long)s * (3 * DIM) + d4;
        float4 qv = *(const float4*)rp;
        float4 kv = *(const float4*)(rp + DIM);
        float4 vv = *(const float4*)(rp + 2 * DIM);
        qv.x *= scale; qv.y *= scale; qv.z *= scale; qv.w *= scale;

        float qa[4] = {qv.x, qv.y, qv.z, qv.w};
        float ka[4] = {kv.x, kv.y, kv.z, kv.w};
        float va[4] = {vv.x, vv.y, vv.z, vv.w};
        __nv_bfloat16 qh_[4], ql_[4], kh_[4], kl_[4], vh_[4], vl_[4];
        #pragma unroll
        for (int j = 0; j < 4; j++) {
            qh_[j] = __float2bfloat16(qa[j]);
            ql_[j] = __float2bfloat16(qa[j] - __bfloat162float(qh_[j]));
            kh_[j] = __float2bfloat16(ka[j]);
            kl_[j] = __float2bfloat16(ka[j] - __bfloat162float(kh_[j]));
            vh_[j] = __float2bfloat16(va[j]);
            vl_[j] = __float2bfloat16(va[j] - __bfloat162float(vh_[j]));
        }
        uint32_t ro = (uint32_t)s * 80 + d4 * 2;
        *(__nv_bfloat162*)(smem + AQH + ro)     = __nv_bfloat162(qh_[0], qh_[1]);
        *(__nv_bfloat162*)(smem + AQH + ro + 4) = __nv_bfloat162(qh_[2], qh_[3]);
        *(__nv_bfloat162*)(smem + AQL + ro)     = __nv_bfloat162(ql_[0], ql_[1]);
        *(__nv_bfloat162*)(smem + AQL + ro + 4) = __nv_bfloat162(ql_[2], ql_[3]);
        *(__nv_bfloat162*)(smem + AKH + ro)     = __nv_bfloat162(kh_[0], kh_[1]);
        *(__nv_bfloat162*)(smem + AKH + ro + 4) = __nv_bfloat162(kh_[2], kh_[3]);
        *(__nv_bfloat162*)(smem + AKL + ro)     = __nv_bfloat162(kl_[0], kl_[1]);
        *(__nv_bfloat162*)(smem + AKL + ro + 4) = __nv_bfloat162(kl_[2], kl_[3]);
        *(__nv_bfloat162*)(smem + AVH + ro)     = __nv_bfloat162(vh_[0], vh_[1]);
        *(__nv_bfloat162*)(smem + AVH + ro + 4) = __nv_bfloat162(vh_[2], vh_[3]);
        *(__nv_bfloat162*)(smem + AVL + ro)     = __nv_bfloat162(vl_[0], vl_[1]);
        *(__nv_bfloat162*)(smem + AVL + ro + 4) = __nv_bfloat162(vl_[2], vl_[3]);
    }
    __syncthreads();

    float accs[8][4];
    #pragma unroll
    for (int ni = 0; ni < 8; ni++)
        #pragma unroll
        for (int j = 0; j < 4; j++) accs[ni][j] = 0.f;

    const uint32_t aQ = sb + AQH +
        (uint32_t)(w * 16 + (lane & 15)) * 80 + (lane >> 4) * 16;
    const int bg = lane >> 3, bfr = bg >> 1, bkh = bg & 1;
    const uint32_t bK = sb + AKH +
        (uint32_t)(bfr * 8 + (lane & 7)) * 80 + bkh * 16;

    #pragma unroll
    for (int kk = 0; kk < 2; kk++) {
        uint32_t ah[4], al[4];
        LDSM4(ah, aQ + kk * 32);
        LDSM4(al, aQ + (AQL - AQH) + kk * 32);
        #pragma unroll
        for (int p = 0; p < 4; p++) {
            uint32_t bh[4], bl[4];
            uint32_t addr = bK + (uint32_t)p * 16 * 80 + kk * 32;
            LDSM4(bh, addr);
            LDSM4(bl, addr + (AKL - AKH));
            #pragma unroll
            for (int q2 = 0; q2 < 2; q2++) {
                const int ni = p * 2 + q2, rb = q2 * 2;
                MMA16816(accs[ni], ah, bh[rb], bh[rb + 1]);
                MMA16816(accs[ni], ah, bl[rb], bl[rb + 1]);
                MMA16816(accs[ni], al, bh[rb], bh[rb + 1]);
            }
        }
    }

    const int r1 = lane >> 2, tq = lane & 3;
    const int row1 = w * 16 + r1, row2 = row1 + 8;
    {
        // padded table: unconditional vectorized adds (pads are -1e30)
        const float* bmr1 = bm_tab + ((long)(b & 3) * HEADS + h) * (64 * 64)
                            + (long)row1 * 64;
        const float* bmr2 = bmr1 + 8 * 64;
        #pragma unroll
        for (int ni = 0; ni < 8; ni++) {
            const int c0 = ni * 8 + tq * 2;
            float2 u1 = *(const float2*)(bmr1 + c0);
            float2 u2 = *(const float2*)(bmr2 + c0);
            accs[ni][0] += u1.x; accs[ni][1] += u1.y;
            accs[ni][2] += u2.x; accs[ni][3] += u2.y;
        }
        float m1 = -1e30f, m2 = -1e30f;
        #pragma unroll
        for (int ni = 0; ni < 8; ni++) {
            m1 = fmaxf(m1, fmaxf(accs[ni][0], accs[ni][1]));
            m2 = fmaxf(m2, fmaxf(accs[ni][2], accs[ni][3]));
        }
        m1 = fmaxf(m1, __shfl_xor_sync(0xffffffff, m1, 1));
        m1 = fmaxf(m1, __shfl_xor_sync(0xffffffff, m1, 2));
        m2 = fmaxf(m2, __shfl_xor_sync(0xffffffff, m2, 1));
        m2 = fmaxf(m2, __shfl_xor_sync(0xffffffff, m2, 2));
        float s1 = 0.f, s2 = 0.f;
        #pragma unroll
        for (int ni = 0; ni < 8; ni++) {
            accs[ni][0] = __expf(accs[ni][0] - m1);
            accs[ni][1] = __expf(accs[ni][1] - m1);
            accs[ni][2] = __expf(accs[ni][2] - m2);
            accs[ni][3] = __expf(accs[ni][3] - m2);
            s1 += accs[ni][0] + accs[ni][1];
            s2 += accs[ni][2] + accs[ni][3];
        }
        s1 += __shfl_xor_sync(0xffffffff, s1, 1);
        s1 += __shfl_xor_sync(0xffffffff, s1, 2);
        s2 += __shfl_xor_sync(0xffffffff, s2, 1);
        s2 += __shfl_xor_sync(0xffffffff, s2, 2);
        const float i1 = 1.0f / s1, i2 = 1.0f / s2;
        #pragma unroll
        for (int ni = 0; ni < 8; ni++) {
            accs[ni][0] *= i1; accs[ni][1] *= i1;
            accs[ni][2] *= i2; accs[ni][3] *= i2;
        }
    }

    float acco[4][4];
    #pragma unroll
    for (int ni = 0; ni < 4; ni++)
        #pragma unroll
        for (int j = 0; j < 4; j++) acco[ni][j] = 0.f;

    const int vt = lane >> 3, vlr = lane & 7;
    const uint32_t bVt = sb + AVH +
        (uint32_t)((vt & 1) * 8 + vlr) * 80 + (vt >> 1) * 16;

    #pragma unroll
    for (int ks = 0; ks < 4; ks++) {
        uint32_t ph_[4], pl_[4];
        #pragma unroll
        for (int half = 0; half < 2; half++) {
            const int ni = 2 * ks + half;
            float p0 = accs[ni][0], p1 = accs[ni][1];
            float p2 = accs[ni][2], p3 = accs[ni][3];
            __nv_bfloat16 h0 = __float2bfloat16(p0), h1 = __float2bfloat16(p1);
            __nv_bfloat16 h2 = __float2bfloat16(p2), h3 = __float2bfloat16(p3);
            ph_[half * 2 + 0] = pack_bf162(h0, h1);
            ph_[half * 2 + 1] = pack_bf162(h2, h3);
            pl_[half * 2 + 0] = pack_bf162(
                __float2bfloat16(p0 - __bfloat162float(h0)),
                __float2bfloat16(p1 - __bfloat162float(h1)));
            pl_[half * 2 + 1] = pack_bf162(
                __float2bfloat16(p2 - __bfloat162float(h2)),
                __float2bfloat16(p3 - __bfloat162float(h3)));
        }
        #pragma unroll
        for (int p = 0; p < 2; p++) {
            uint32_t bh[4], bl[4];
            uint32_t addr = bVt + (uint32_t)ks * (16 * 80) + p * 32;
            LDSM4T(bh, addr);
            LDSM4T(bl, addr + (AVL - AVH));
            #pragma unroll
            for (int q2 = 0; q2 < 2; q2++) {
                const int ni = p * 2 + q2, rb = q2 * 2;
                MMA16816(acco[ni], ph_, bh[rb], bh[rb + 1]);
                MMA16816(acco[ni], ph_, bl[rb], bl[rb + 1]);
                MMA16816(acco[ni], pl_, bh[rb], bh[rb + 1]);
            }
        }
    }

    #pragma unroll
    for (int ni = 0; ni < 4; ni++) {
        const int d0 = ni * 8 + tq * 2;
        if (row1 < SS) {
            long idx = ((long)b * SS + row1) * DIM + h * HD + d0;
            __nv_bfloat16 h0 = __float2bfloat16(acco[ni][0]);
            __nv_bfloat16 h1 = __float2bfloat16(acco[ni][1]);
            *(__nv_bfloat162*)(out_hi + idx) = __nv_bfloat162(h0, h1);
            *(__nv_bfloat162*)(out_lo + idx) = __nv_bfloat162(
                __float2bfloat16(acco[ni][0] - __bfloat162float(h0)),
                __float2bfloat16(acco[ni][1] - __bfloat162float(h1)));
        }
        if (row2 < SS) {
            long idx = ((long)b * SS + row2) * DIM + h * HD + d0;
            __nv_bfloat16 h2 = __float2bfloat16(acco[ni][2]);
            __nv_bfloat16 h3 = __float2bfloat16(acco[ni][3]);
            *(__nv_bfloat162*)(out_hi + idx) = __nv_bfloat162(h2, h3);
            *(__nv_bfloat162*)(out_lo + idx) = __nv_bfloat162(
                __float2bfloat16(acco[ni][2] - __bfloat162float(h2)),
                __float2bfloat16(acco[ni][3] - __bfloat162float(h3)));
        }
    }
}

// ---------------------------------------------------------------------------
extern "C" void kernel_launch(void* const* d_in, const int* in_sizes, int n_in,
                              void* d_out, int out_size)
{
    const float* x          = (const float*)d_in[0];
    const float* mask       = (const float*)d_in[1];
    const float* w_qkv      = (const float*)d_in[2];
    const float* b_qkv      = (const float*)d_in[3];
    const float* w_proj     = (const float*)d_in[4];
    const float* b_proj     = (const float*)d_in[5];
    const float* bias_table = (const float*)d_in[6];
    const int*   rel_idx    = (const int*)d_in[7];
    float* out = (float*)d_out;

    __nv_bfloat16 *xh, *xl, *ah, *al, *wqh, *wql, *wph, *wpl;
    float *qkv, *bm;
    cudaGetSymbolAddress((void**)&xh,  g_xh);
    cudaGetSymbolAddress((void**)&xl,  g_xl);
    cudaGetSymbolAddress((void**)&qkv, g_qkv);
    cudaGetSymbolAddress((void**)&ah,  g_ah);
    cudaGetSymbolAddress((void**)&al,  g_al);
    cudaGetSymbolAddress((void**)&wqh, g_wqh);
    cudaGetSymbolAddress((void**)&wql, g_wql);
    cudaGetSymbolAddress((void**)&wph, g_wph);
    cudaGetSymbolAddress((void**)&wpl, g_wpl);
    cudaGetSymbolAddress((void**)&bm,  g_bm);

    cudaFuncSetAttribute(gemm_bf16x3_mma,
                         cudaFuncAttributeMaxDynamicSharedMemorySize, GEMM_SMEM);
    cudaFuncSetAttribute(attn_mma_kernel,
                         cudaFuncAttributeMaxDynamicSharedMemorySize, ATTN_SMEM);

    // 1) input/weight splits
    {
        long n4 = (long)MROWS * KDIM / 4;
        split_kernel<<<2048, 256>>>(x, xh, xl, n4);
        wsplit_kernel<<<(3 * DIM * KDIM) / 256, 256>>>(w_qkv, wqh, wql, 3 * DIM,
                                                       3 * DIM * KDIM);
        wsplit_kernel<<<(DIM * KDIM) / 256, 256>>>(w_proj, wph, wpl, DIM, DIM * KDIM);
    }

    // 2) QKV GEMM — stays launch #4 for ncu capture
    {
        dim3 grid(12, 784);
        gemm_bf16x3_mma<<<grid, 256, GEMM_SMEM>>>(xh, xl, wqh, wql, b_qkv, qkv,
                                                  3 * DIM);
    }

    // 3) padded bias+mask table
    {
        int bmtot = 4 * HEADS * 64 * 64;
        biasmask_kernel<<<(bmtot + 255) / 256, 256>>>(bias_table, rel_idx, mask, bm);
    }

    // 4) MMA window attention (register-P)
    {
        dim3 grid(BTOT, HEADS);
        attn_mma_kernel<<<grid, 128, ATTN_SMEM>>>(qkv, bm, ah, al);
    }

    // 5) Proj GEMM (fp32 out)
    {
        dim3 grid(4, 784);
        gemm_bf16x3_mma<<<grid, 256, GEMM_SMEM>>>(ah, al, wph, wpl, b_proj, out,
                                                  DIM);
    }
}

// round 17
// speedup vs baseline: 1.2743x; 1.0808x over previous
#include <cuda_runtime.h>
#include <cuda_bf16.h>
#include <cuda_fp16.h>
#include <cstdint>

#define DIM   512
#define HEADS 16
#define HD    32
#define SS    49
#define BTOT  2048
#define MROWS (BTOT * SS)   // 100352 = 784 * 128
#define KDIM  512

// ---------------- scratch (__device__ globals; allocation-free rule) -------
__device__ __nv_bfloat16 g_xh[(size_t)MROWS * KDIM];
__device__ __nv_bfloat16 g_xl[(size_t)MROWS * KDIM];
__device__ float         g_qkv[(size_t)MROWS * 3 * DIM];
__device__ __half        g_a16[(size_t)MROWS * DIM];      // attention out, fp16
__device__ __nv_bfloat16 g_wqh[(size_t)3 * DIM * KDIM];   // transposed [1536][512]
__device__ __nv_bfloat16 g_wql[(size_t)3 * DIM * KDIM];
__device__ __half        g_wp16h[(size_t)DIM * KDIM];     // proj W fp16 hi (transposed)
__device__ __half        g_wp16l[(size_t)DIM * KDIM];     // proj W fp16 lo
__device__ float         g_bm[4 * HEADS * 64 * 64];       // PADDED bias+mask

// ---------------- PTX helpers ---------------------------------------------
__device__ __forceinline__ uint32_t smem_u32(const void* p) {
    uint32_t a;
    asm("{ .reg .u64 t; cvta.to.shared.u64 t, %1; cvt.u32.u64 %0, t; }"
        : "=r"(a) : "l"(p));
    return a;
}
__device__ __forceinline__ void cpa16(uint32_t s, const void* g) {
    asm volatile("cp.async.cg.shared.global [%0], [%1], 16;" :: "r"(s), "l"(g));
}
#define CP_COMMIT() asm volatile("cp.async.commit_group;")
#define CP_WAIT1()  asm volatile("cp.async.wait_group 1;")
#define CP_WAIT0()  asm volatile("cp.async.wait_group 0;")

#define LDSM4(r, addr) \
    asm volatile("ldmatrix.sync.aligned.m8n8.x4.shared.b16 {%0,%1,%2,%3}, [%4];" \
        : "=r"((r)[0]), "=r"((r)[1]), "=r"((r)[2]), "=r"((r)[3]) : "r"(addr))

#define LDSM4T(r, addr) \
    asm volatile("ldmatrix.sync.aligned.m8n8.x4.trans.shared.b16 {%0,%1,%2,%3}, [%4];" \
        : "=r"((r)[0]), "=r"((r)[1]), "=r"((r)[2]), "=r"((r)[3]) : "r"(addr))

#define MMA16816(d, a, b0, b1) \
    asm volatile("mma.sync.aligned.m16n8k16.row.col.f32.bf16.bf16.f32 " \
        "{%0,%1,%2,%3}, {%4,%5,%6,%7}, {%8,%9}, {%0,%1,%2,%3};" \
        : "+f"((d)[0]), "+f"((d)[1]), "+f"((d)[2]), "+f"((d)[3]) \
        : "r"((a)[0]), "r"((a)[1]), "r"((a)[2]), "r"((a)[3]), "r"(b0), "r"(b1))

#define MMA16816H(d, a, b0, b1) \
    asm volatile("mma.sync.aligned.m16n8k16.row.col.f32.f16.f16.f32 " \
        "{%0,%1,%2,%3}, {%4,%5,%6,%7}, {%8,%9}, {%0,%1,%2,%3};" \
        : "+f"((d)[0]), "+f"((d)[1]), "+f"((d)[2]), "+f"((d)[3]) \
        : "r"((a)[0]), "r"((a)[1]), "r"((a)[2]), "r"((a)[3]), "r"(b0), "r"(b1))

__device__ __forceinline__ uint32_t pack_bf162(__nv_bfloat16 a, __nv_bfloat16 b) {
    __nv_bfloat162 t(a, b);
    return *(uint32_t*)&t;
}

// ---------------------------------------------------------------------------
// bf16x3 HMMA GEMM (frozen R15 shape): C = (Ah+Al)@(Bh+Bl)^T + bias (fp32)
// ---------------------------------------------------------------------------
#define TSTRIDE     64
#define TILE_BYTES  (128 * TSTRIDE)          // 8192
#define STAGE_BYTES (4 * TILE_BYTES)         // 32768
#define GEMM_SMEM   (3 * STAGE_BYTES)        // 98304

__global__ __launch_bounds__(256, 2) void gemm_bf16x3_mma(
    const __nv_bfloat16* __restrict__ Ah, const __nv_bfloat16* __restrict__ Al,
    const __nv_bfloat16* __restrict__ Bh, const __nv_bfloat16* __restrict__ Bl,
    const float* __restrict__ bias, float* __restrict__ C, int N)
{
    extern __shared__ char smem[];
    const uint32_t sb = smem_u32(smem);
    const int tid  = threadIdx.x;
    const int lane = tid & 31, wid = tid >> 5;
    const int wr = wid >> 2, wc = wid & 3;
    const long m0 = (long)blockIdx.y * 128;
    const int  n0 = blockIdx.x * 128;

    auto load_stage = [&](int s, int k0) {
        const uint32_t base = sb + (uint32_t)s * STAGE_BYTES;
        #pragma unroll
        for (int half = 0; half < 2; half++) {
            const int chunk = tid + half * 256;
            const int r = chunk >> 2, c = chunk & 3;
            const int cs = c ^ ((r >> 1) & 3);
            const uint32_t off = (uint32_t)r * TSTRIDE + cs * 16;
            const long aIdx = (m0 + r) * (long)KDIM + k0 + c * 8;
            const long bIdx = ((long)n0 + r) * (long)KDIM + k0 + c * 8;
            cpa16(base + off,                  (const char*)(Ah + aIdx));
            cpa16(base + TILE_BYTES + off,     (const char*)(Al + aIdx));
            cpa16(base + 2 * TILE_BYTES + off, (const char*)(Bh + bIdx));
            cpa16(base + 3 * TILE_BYTES + off, (const char*)(Bl + bIdx));
        }
    };

    float acc[4][4][4];
    #pragma unroll
    for (int mi = 0; mi < 4; mi++)
        #pragma unroll
        for (int ni = 0; ni < 4; ni++)
            #pragma unroll
            for (int j = 0; j < 4; j++) acc[mi][ni][j] = 0.f;

    const int sA = ((lane & 15) >> 1) & 3;
    const int bg = lane >> 3, bfr = bg >> 1, bkh = bg & 1;
    const int sB = ((lane & 7) >> 1) & 3;
    const uint32_t cA[2] = { (uint32_t)(((lane >> 4) ^ sA) * 16),
                             (uint32_t)(((2 + (lane >> 4)) ^ sA) * 16) };
    const uint32_t cB[2] = { (uint32_t)((bkh ^ sB) * 16),
                             (uint32_t)(((2 + bkh) ^ sB) * 16) };
    const uint32_t aRowOff = (uint32_t)(wr * 64 + (lane & 15)) * TSTRIDE;
    const uint32_t bRowOff = 2 * TILE_BYTES +
        (uint32_t)(wc * 32 + bfr * 8 + (lane & 7)) * TSTRIDE;

    auto compute_half = [&](int s, int kk) {
        const uint32_t base = sb + (uint32_t)s * STAGE_BYTES;
        uint32_t bh[2][4], bl[2][4];
        #pragma unroll
        for (int p = 0; p < 2; p++) {
            uint32_t addr = base + bRowOff + (uint32_t)p * 16 * TSTRIDE + cB[kk];
            LDSM4(bh[p], addr);
            LDSM4(bl[p], addr + TILE_BYTES);
        }
        #pragma unroll
        for (int mi = 0; mi < 4; mi++) {
            uint32_t aaddr = base + aRowOff + (uint32_t)mi * 16 * TSTRIDE + cA[kk];
            uint32_t ah[4];
            LDSM4(ah, aaddr);
            #pragma unroll
            for (int p = 0; p < 2; p++)
                #pragma unroll
                for (int q2 = 0; q2 < 2; q2++) {
                    const int ni = p * 2 + q2, rb = q2 * 2;
                    MMA16816(acc[mi][ni], ah, bh[p][rb], bh[p][rb + 1]);
                    MMA16816(acc[mi][ni], ah, bl[p][rb], bl[p][rb + 1]);
                }
            uint32_t al[4];
            LDSM4(al, aaddr + TILE_BYTES);
            #pragma unroll
            for (int p = 0; p < 2; p++)
                #pragma unroll
                for (int q2 = 0; q2 < 2; q2++) {
                    const int ni = p * 2 + q2, rb = q2 * 2;
                    MMA16816(acc[mi][ni], al, bh[p][rb], bh[p][rb + 1]);
                }
        }
    };

    load_stage(0, 0);  CP_COMMIT();
    load_stage(1, 32); CP_COMMIT();
    int sCur = 0, sNext = 2;
    #pragma unroll 1
    for (int kt = 0; kt < 16; kt++) {
        if (kt < 15) { CP_WAIT1(); } else { CP_WAIT0(); }
        __syncthreads();
        compute_half(sCur, 0);
        if (kt + 2 < 16) {
            load_stage(sNext, (kt + 2) * 32);
            CP_COMMIT();
        }
        compute_half(sCur, 1);
        sCur  = (sCur == 2)  ? 0 : sCur + 1;
        sNext = (sNext == 2) ? 0 : sNext + 1;
    }

    const int r0 = lane >> 2, cpos = (lane & 3) * 2;
    #pragma unroll
    for (int ni = 0; ni < 4; ni++) {
        const int col = n0 + wc * 32 + ni * 8 + cpos;
        const float bx = bias[col], by = bias[col + 1];
        #pragma unroll
        for (int mi = 0; mi < 4; mi++) {
            const long row = m0 + wr * 64 + mi * 16 + r0;
            float2 v0 = {acc[mi][ni][0] + bx, acc[mi][ni][1] + by};
            float2 v1 = {acc[mi][ni][2] + bx, acc[mi][ni][3] + by};
            *(float2*)&C[row * (long)N + col]       = v0;
            *(float2*)&C[(row + 8) * (long)N + col] = v1;
        }
    }
}

// ---------------------------------------------------------------------------
// fp16x2 GEMM for proj: C = A16 @ (Bh+Bl)^T + bias. A single fp16, B split.
// Stage = 3 tiles (A, Bh, Bl) = 24576B; 3 stages = 73728B. 2 CTAs/SM.
// ---------------------------------------------------------------------------
#define STAGE2_BYTES (3 * TILE_BYTES)        // 24576
#define GEMM2_SMEM   (3 * STAGE2_BYTES)      // 73728

__global__ __launch_bounds__(256, 2) void gemm_f16x2_mma(
    const __half* __restrict__ A16,
    const __half* __restrict__ Bh, const __half* __restrict__ Bl,
    const float* __restrict__ bias, float* __restrict__ C, int N)
{
    extern __shared__ char smem[];
    const uint32_t sb = smem_u32(smem);
    const int tid  = threadIdx.x;
    const int lane = tid & 31, wid = tid >> 5;
    const int wr = wid >> 2, wc = wid & 3;
    const long m0 = (long)blockIdx.y * 128;
    const int  n0 = blockIdx.x * 128;

    auto load_stage = [&](int s, int k0) {
        const uint32_t base = sb + (uint32_t)s * STAGE2_BYTES;
        #pragma unroll
        for (int half = 0; half < 2; half++) {
            const int chunk = tid + half * 256;
            const int r = chunk >> 2, c = chunk & 3;
            const int cs = c ^ ((r >> 1) & 3);
            const uint32_t off = (uint32_t)r * TSTRIDE + cs * 16;
            const long aIdx = (m0 + r) * (long)KDIM + k0 + c * 8;
            const long bIdx = ((long)n0 + r) * (long)KDIM + k0 + c * 8;
            cpa16(base + off,                  (const char*)(A16 + aIdx));
            cpa16(base + TILE_BYTES + off,     (const char*)(Bh + bIdx));
            cpa16(base + 2 * TILE_BYTES + off, (const char*)(Bl + bIdx));
        }
    };

    float acc[4][4][4];
    #pragma unroll
    for (int mi = 0; mi < 4; mi++)
        #pragma unroll
        for (int ni = 0; ni < 4; ni++)
            #pragma unroll
            for (int j = 0; j < 4; j++) acc[mi][ni][j] = 0.f;

    const int sA = ((lane & 15) >> 1) & 3;
    const int bg = lane >> 3, bfr = bg >> 1, bkh = bg & 1;
    const int sB = ((lane & 7) >> 1) & 3;
    const uint32_t cA[2] = { (uint32_t)(((lane >> 4) ^ sA) * 16),
                             (uint32_t)(((2 + (lane >> 4)) ^ sA) * 16) };
    const uint32_t cB[2] = { (uint32_t)((bkh ^ sB) * 16),
                             (uint32_t)(((2 + bkh) ^ sB) * 16) };
    const uint32_t aRowOff = (uint32_t)(wr * 64 + (lane & 15)) * TSTRIDE;
    const uint32_t bRowOff = TILE_BYTES +
        (uint32_t)(wc * 32 + bfr * 8 + (lane & 7)) * TSTRIDE;

    auto compute_half = [&](int s, int kk) {
        const uint32_t base = sb + (uint32_t)s * STAGE2_BYTES;
        uint32_t bh[2][4], bl[2][4];
        #pragma unroll
        for (int p = 0; p < 2; p++) {
            uint32_t addr = base + bRowOff + (uint32_t)p * 16 * TSTRIDE + cB[kk];
            LDSM4(bh[p], addr);
            LDSM4(bl[p], addr + TILE_BYTES);
        }
        #pragma unroll
        for (int mi = 0; mi < 4; mi++) {
            uint32_t aaddr = base + aRowOff + (uint32_t)mi * 16 * TSTRIDE + cA[kk];
            uint32_t ah[4];
            LDSM4(ah, aaddr);
            #pragma unroll
            for (int p = 0; p < 2; p++)
                #pragma unroll
                for (int q2 = 0; q2 < 2; q2++) {
                    const int ni = p * 2 + q2, rb = q2 * 2;
                    MMA16816H(acc[mi][ni], ah, bh[p][rb], bh[p][rb + 1]);
                    MMA16816H(acc[mi][ni], ah, bl[p][rb], bl[p][rb + 1]);
                }
        }
    };

    load_stage(0, 0);  CP_COMMIT();
    load_stage(1, 32); CP_COMMIT();
    int sCur = 0, sNext = 2;
    #pragma unroll 1
    for (int kt = 0; kt < 16; kt++) {
        if (kt < 15) { CP_WAIT1(); } else { CP_WAIT0(); }
        __syncthreads();
        compute_half(sCur, 0);
        if (kt + 2 < 16) {
            load_stage(sNext, (kt + 2) * 32);
            CP_COMMIT();
        }
        compute_half(sCur, 1);
        sCur  = (sCur == 2)  ? 0 : sCur + 1;
        sNext = (sNext == 2) ? 0 : sNext + 1;
    }

    const int r0 = lane >> 2, cpos = (lane & 3) * 2;
    #pragma unroll
    for (int ni = 0; ni < 4; ni++) {
        const int col = n0 + wc * 32 + ni * 8 + cpos;
        const float bx = bias[col], by = bias[col + 1];
        #pragma unroll
        for (int mi = 0; mi < 4; mi++) {
            const long row = m0 + wr * 64 + mi * 16 + r0;
            float2 v0 = {acc[mi][ni][0] + bx, acc[mi][ni][1] + by};
            float2 v1 = {acc[mi][ni][2] + bx, acc[mi][ni][3] + by};
            *(float2*)&C[row * (long)N + col]       = v0;
            *(float2*)&C[(row + 8) * (long)N + col] = v1;
        }
    }
}

// ---------------------------------------------------------------------------
// prep kernels
// ---------------------------------------------------------------------------
__global__ void split_kernel(const float* __restrict__ in,
                             __nv_bfloat16* __restrict__ hi,
                             __nv_bfloat16* __restrict__ lo, long n4)
{
    long i = (long)blockIdx.x * blockDim.x + threadIdx.x;
    const long stride = (long)gridDim.x * blockDim.x;
    for (; i < n4; i += stride) {
        float4 v = ((const float4*)in)[i];
        __nv_bfloat16 h0 = __float2bfloat16(v.x);
        __nv_bfloat16 h1 = __float2bfloat16(v.y);
        __nv_bfloat16 h2 = __float2bfloat16(v.z);
        __nv_bfloat16 h3 = __float2bfloat16(v.w);
        __nv_bfloat162* hp = (__nv_bfloat162*)hi + 2 * i;
        hp[0] = __nv_bfloat162(h0, h1);
        hp[1] = __nv_bfloat162(h2, h3);
        __nv_bfloat162* lp = (__nv_bfloat162*)lo + 2 * i;
        lp[0] = __nv_bfloat162(__float2bfloat16(v.x - __bfloat162float(h0)),
                               __float2bfloat16(v.y - __bfloat162float(h1)));
        lp[1] = __nv_bfloat162(__float2bfloat16(v.z - __bfloat162float(h2)),
                               __float2bfloat16(v.w - __bfloat162float(h3)));
    }
}

__global__ void wsplit_kernel(const float* __restrict__ w,
                              __nv_bfloat16* __restrict__ hi,
                              __nv_bfloat16* __restrict__ lo, int N, int total)
{
    int i = blockIdx.x * 256 + threadIdx.x;
    if (i >= total) return;
    int k = i & (KDIM - 1);
    int n = i >> 9;
    float v = w[(long)k * N + n];
    __nv_bfloat16 h = __float2bfloat16(v);
    hi[i] = h;
    lo[i] = __float2bfloat16(v - __bfloat162float(h));
}

// proj weights -> fp16 (hi, lo), transposed
__global__ void wsplit16_kernel(const float* __restrict__ w,
                                __half* __restrict__ hi,
                                __half* __restrict__ lo, int N, int total)
{
    int i = blockIdx.x * 256 + threadIdx.x;
    if (i >= total) return;
    int k = i & (KDIM - 1);
    int n = i >> 9;
    float v = w[(long)k * N + n];
    __half h = __float2half(v);
    hi[i] = h;
    lo[i] = __float2half(v - __half2float(h));
}

__global__ void biasmask_kernel(const float* __restrict__ bias_table,
                                const int* __restrict__ rel_idx,
                                const float* __restrict__ mask,
                                float* __restrict__ bm)
{
    int idx = blockIdx.x * 256 + threadIdx.x;
    const int total = 4 * HEADS * 64 * 64;
    if (idx >= total) return;
    int c = idx & 63;
    int r = (idx >> 6) & 63;
    int h = (idx >> 12) & (HEADS - 1);
    int w = idx >> 16;
    float val = -1e30f;
    if (r < SS && c < SS)
        val = bias_table[rel_idx[r * SS + c] * HEADS + h] + mask[w * SS * SS + r * SS + c];
    bm[idx] = val;
}

// ---------------------------------------------------------------------------
// MMA window attention (register-P). Output: SINGLE fp16 array. 30720B smem.
// ---------------------------------------------------------------------------
#define AQH   0
#define AQL   5120
#define AKH   10240
#define AKL   15360
#define AVH   20480
#define AVL   25600
#define ATTN_SMEM 30720

__global__ __launch_bounds__(128) void attn_mma_kernel(
    const float* __restrict__ qkv, const float* __restrict__ bm_tab,
    __half* __restrict__ out16)
{
    extern __shared__ char smem[];
    const uint32_t sb = smem_u32(smem);
    const int b = blockIdx.x, h = blockIdx.y;
    const int tid = threadIdx.x, lane = tid & 31, w = tid >> 5;

    for (int i = tid; i < 300; i += 128) {
        int r = 49 + i / 20, c = (i % 20) * 4;
        *(uint32_t*)(smem + AQH + r * 80 + c) = 0;
        *(uint32_t*)(smem + AQL + r * 80 + c) = 0;
        *(uint32_t*)(smem + AKH + r * 80 + c) = 0;
        *(uint32_t*)(smem + AKL + r * 80 + c) = 0;
    }
    for (int i = tid; i < 1280; i += 128) {
        *(uint32_t*)(smem + AVH + i * 4) = 0;
        *(uint32_t*)(smem + AVL + i * 4) = 0;
    }

    const float scale = 0.17677669529663687f;
    const float* base = qkv + (long)b * SS * (3 * DIM) + h * HD;
    for (int e = tid; e < 392; e += 128) {
        int s = e >> 3, d4 = (e & 7) * 4;
        const float* rp = base + (long)s * (3 * DIM) + d4;
        float4 qv = *(const float4*)rp;
        float4 kv = *(const float4*)(rp + DIM);
        float4 vv = *(const float4*)(rp + 2 * DIM);
        qv.x *= scale; qv.y *= scale; qv.z *= scale; qv.w *= scale;

        float qa[4] = {qv.x, qv.y, qv.z, qv.w};
        float ka[4] = {kv.x, kv.y, kv.z, kv.w};
        float va[4] = {vv.x, vv.y, vv.z, vv.w};
        __nv_bfloat16 qh_[4], ql_[4], kh_[4], kl_[4], vh_[4], vl_[4];
        #pragma unroll
        for (int j = 0; j < 4; j++) {
            qh_[j] = __float2bfloat16(qa[j]);
            ql_[j] = __float2bfloat16(qa[j] - __bfloat162float(qh_[j]));
            kh_[j] = __float2bfloat16(ka[j]);
            kl_[j] = __float2bfloat16(ka[j] - __bfloat162float(kh_[j]));
            vh_[j] = __float2bfloat16(va[j]);
            vl_[j] = __float2bfloat16(va[j] - __bfloat162float(vh_[j]));
        }
        uint32_t ro = (uint32_t)s * 80 + d4 * 2;
        *(__nv_bfloat162*)(smem + AQH + ro)     = __nv_bfloat162(qh_[0], qh_[1]);
        *(__nv_bfloat162*)(smem + AQH + ro + 4) = __nv_bfloat162(qh_[2], qh_[3]);
        *(__nv_bfloat162*)(smem + AQL + ro)     = __nv_bfloat162(ql_[0], ql_[1]);
        *(__nv_bfloat162*)(smem + AQL + ro + 4) = __nv_bfloat162(ql_[2], ql_[3]);
        *(__nv_bfloat162*)(smem + AKH + ro)     = __nv_bfloat162(kh_[0], kh_[1]);
        *(__nv_bfloat162*)(smem + AKH + ro + 4) = __nv_bfloat162(kh_[2], kh_[3]);
        *(__nv_bfloat162*)(smem + AKL + ro)     = __nv_bfloat162(kl_[0], kl_[1]);
        *(__nv_bfloat162*)(smem + AKL + ro + 4) = __nv_bfloat162(kl_[2], kl_[3]);
        *(__nv_bfloat162*)(smem + AVH + ro)     = __nv_bfloat162(vh_[0], vh_[1]);
        *(__nv_bfloat162*)(smem + AVH + ro + 4) = __nv_bfloat162(vh_[2], vh_[3]);
        *(__nv_bfloat162*)(smem + AVL + ro)     = __nv_bfloat162(vl_[0], vl_[1]);
        *(__nv_bfloat162*)(smem + AVL + ro + 4) = __nv_bfloat162(vl_[2], vl_[3]);
    }
    __syncthreads();

    float accs[8][4];
    #pragma unroll
    for (int ni = 0; ni < 8; ni++)
        #pragma unroll
        for (int j = 0; j < 4; j++) accs[ni][j] = 0.f;

    const uint32_t aQ = sb + AQH +
        (uint32_t)(w * 16 + (lane & 15)) * 80 + (lane >> 4) * 16;
    const int bg = lane >> 3, bfr = bg >> 1, bkh = bg & 1;
    const uint32_t bK = sb + AKH +
        (uint32_t)(bfr * 8 + (lane & 7)) * 80 + bkh * 16;

    #pragma unroll
    for (int kk = 0; kk < 2; kk++) {
        uint32_t ah[4], al[4];
        LDSM4(ah, aQ + kk * 32);
        LDSM4(al, aQ + (AQL - AQH) + kk * 32);
        #pragma unroll
        for (int p = 0; p < 4; p++) {
            uint32_t bh[4], bl[4];
            uint32_t addr = bK + (uint32_t)p * 16 * 80 + kk * 32;
            LDSM4(bh, addr);
            LDSM4(bl, addr + (AKL - AKH));
            #pragma unroll
            for (int q2 = 0; q2 < 2; q2++) {
                const int ni = p * 2 + q2, rb = q2 * 2;
                MMA16816(accs[ni], ah, bh[rb], bh[rb + 1]);
                MMA16816(accs[ni], ah, bl[rb], bl[rb + 1]);
                MMA16816(accs[ni], al, bh[rb], bh[rb + 1]);
            }
        }
    }

    const int r1 = lane >> 2, tq = lane & 3;
    const int row1 = w * 16 + r1, row2 = row1 + 8;
    {
        const float* bmr1 = bm_tab + ((long)(b & 3) * HEADS + h) * (64 * 64)
                            + (long)row1 * 64;
        const float* bmr2 = bmr1 + 8 * 64;
        #pragma unroll
        for (int ni = 0; ni < 8; ni++) {
            const int c0 = ni * 8 + tq * 2;
            float2 u1 = *(const float2*)(bmr1 + c0);
            float2 u2 = *(const float2*)(bmr2 + c0);
            accs[ni][0] += u1.x; accs[ni][1] += u1.y;
            accs[ni][2] += u2.x; accs[ni][3] += u2.y;
        }
        float m1 = -1e30f, m2 = -1e30f;
        #pragma unroll
        for (int ni = 0; ni < 8; ni++) {
            m1 = fmaxf(m1, fmaxf(accs[ni][0], accs[ni][1]));
            m2 = fmaxf(m2, fmaxf(accs[ni][2], accs[ni][3]));
        }
        m1 = fmaxf(m1, __shfl_xor_sync(0xffffffff, m1, 1));
        m1 = fmaxf(m1, __shfl_xor_sync(0xffffffff, m1, 2));
        m2 = fmaxf(m2, __shfl_xor_sync(0xffffffff, m2, 1));
        m2 = fmaxf(m2, __shfl_xor_sync(0xffffffff, m2, 2));
        float s1 = 0.f, s2 = 0.f;
        #pragma unroll
        for (int ni = 0; ni < 8; ni++) {
            accs[ni][0] = __expf(accs[ni][0] - m1);
            accs[ni][1] = __expf(accs[ni][1] - m1);
            accs[ni][2] = __expf(accs[ni][2] - m2);
            accs[ni][3] = __expf(accs[ni][3] - m2);
            s1 += accs[ni][0] + accs[ni][1];
            s2 += accs[ni][2] + accs[ni][3];
        }
        s1 += __shfl_xor_sync(0xffffffff, s1, 1);
        s1 += __shfl_xor_sync(0xffffffff, s1, 2);
        s2 += __shfl_xor_sync(0xffffffff, s2, 1);
        s2 += __shfl_xor_sync(0xffffffff, s2, 2);
        const float i1 = 1.0f / s1, i2 = 1.0f / s2;
        #pragma unroll
        for (int ni = 0; ni < 8; ni++) {
            accs[ni][0] *= i1; accs[ni][1] *= i1;
            accs[ni][2] *= i2; accs[ni][3] *= i2;
        }
    }

    float acco[4][4];
    #pragma unroll
    for (int ni = 0; ni < 4; ni++)
        #pragma unroll
        for (int j = 0; j < 4; j++) acco[ni][j] = 0.f;

    const int vt = lane >> 3, vlr = lane & 7;
    const uint32_t bVt = sb + AVH +
        (uint32_t)((vt & 1) * 8 + vlr) * 80 + (vt >> 1) * 16;

    #pragma unroll
    for (int ks = 0; ks < 4; ks++) {
        uint32_t ph_[4], pl_[4];
        #pragma unroll
        for (int half = 0; half < 2; half++) {
            const int ni = 2 * ks + half;
            float p0 = accs[ni][0], p1 = accs[ni][1];
            float p2 = accs[ni][2], p3 = accs[ni][3];
            __nv_bfloat16 h0 = __float2bfloat16(p0), h1 = __float2bfloat16(p1);
            __nv_bfloat16 h2 = __float2bfloat16(p2), h3 = __float2bfloat16(p3);
            ph_[half * 2 + 0] = pack_bf162(h0, h1);
            ph_[half * 2 + 1] = pack_bf162(h2, h3);
            pl_[half * 2 + 0] = pack_bf162(
                __float2bfloat16(p0 - __bfloat162float(h0)),
                __float2bfloat16(p1 - __bfloat162float(h1)));
            pl_[half * 2 + 1] = pack_bf162(
                __float2bfloat16(p2 - __bfloat162float(h2)),
                __float2bfloat16(p3 - __bfloat162float(h3)));
        }
        #pragma unroll
        for (int p = 0; p < 2; p++) {
            uint32_t bh[4], bl[4];
            uint32_t addr = bVt + (uint32_t)ks * (16 * 80) + p * 32;
            LDSM4T(bh, addr);
            LDSM4T(bl, addr + (AVL - AVH));
            #pragma unroll
            for (int q2 = 0; q2 < 2; q2++) {
                const int ni = p * 2 + q2, rb = q2 * 2;
                MMA16816(acco[ni], ph_, bh[rb], bh[rb + 1]);
                MMA16816(acco[ni], ph_, bl[rb], bl[rb + 1]);
                MMA16816(acco[ni], pl_, bh[rb], bh[rb + 1]);
            }
        }
    }

    // fp16 single-array output
    #pragma unroll
    for (int ni = 0; ni < 4; ni++) {
        const int d0 = ni * 8 + tq * 2;
        if (row1 < SS) {
            long idx = ((long)b * SS + row1) * DIM + h * HD + d0;
            *(__half2*)(out16 + idx) =
                __half2(__float2half(acco[ni][0]), __float2half(acco[ni][1]));
        }
        if (row2 < SS) {
            long idx = ((long)b * SS + row2) * DIM + h * HD + d0;
            *(__half2*)(out16 + idx) =
                __half2(__float2half(acco[ni][2]), __float2half(acco[ni][3]));
        }
    }
}

// ---------------------------------------------------------------------------
extern "C" void kernel_launch(void* const* d_in, const int* in_sizes, int n_in,
                              void* d_out, int out_size)
{
    const float* x          = (const float*)d_in[0];
    const float* mask       = (const float*)d_in[1];
    const float* w_qkv      = (const float*)d_in[2];
    const float* b_qkv      = (const float*)d_in[3];
    const float* w_proj     = (const float*)d_in[4];
    const float* b_proj     = (const float*)d_in[5];
    const float* bias_table = (const float*)d_in[6];
    const int*   rel_idx    = (const int*)d_in[7];
    float* out = (float*)d_out;

    __nv_bfloat16 *xh, *xl, *wqh, *wql;
    __half *a16, *wp16h, *wp16l;
    float *qkv, *bm;
    cudaGetSymbolAddress((void**)&xh,    g_xh);
    cudaGetSymbolAddress((void**)&xl,    g_xl);
    cudaGetSymbolAddress((void**)&qkv,   g_qkv);
    cudaGetSymbolAddress((void**)&a16,   g_a16);
    cudaGetSymbolAddress((void**)&wqh,   g_wqh);
    cudaGetSymbolAddress((void**)&wql,   g_wql);
    cudaGetSymbolAddress((void**)&wp16h, g_wp16h);
    cudaGetSymbolAddress((void**)&wp16l, g_wp16l);
    cudaGetSymbolAddress((void**)&bm,    g_bm);

    cudaFuncSetAttribute(gemm_bf16x3_mma,
                         cudaFuncAttributeMaxDynamicSharedMemorySize, GEMM_SMEM);
    cudaFuncSetAttribute(gemm_f16x2_mma,
                         cudaFuncAttributeMaxDynamicSharedMemorySize, GEMM2_SMEM);
    cudaFuncSetAttribute(attn_mma_kernel,
                         cudaFuncAttributeMaxDynamicSharedMemorySize, ATTN_SMEM);

    // 1) input/weight splits
    {
        long n4 = (long)MROWS * KDIM / 4;
        split_kernel<<<2048, 256>>>(x, xh, xl, n4);
        wsplit_kernel<<<(3 * DIM * KDIM) / 256, 256>>>(w_qkv, wqh, wql, 3 * DIM,
                                                       3 * DIM * KDIM);
        wsplit16_kernel<<<(DIM * KDIM) / 256, 256>>>(w_proj, wp16h, wp16l, DIM,
                                                     DIM * KDIM);
    }

    // 2) QKV GEMM (bf16x3, fp32 out) — launch #4 for ncu capture
    {
        dim3 grid(12, 784);
        gemm_bf16x3_mma<<<grid, 256, GEMM_SMEM>>>(xh, xl, wqh, wql, b_qkv, qkv,
                                                  3 * DIM);
    }

    // 3) padded bias+mask table
    {
        int bmtot = 4 * HEADS * 64 * 64;
        biasmask_kernel<<<(bmtot + 255) / 256, 256>>>(bias_table, rel_idx, mask, bm);
    }

    // 4) MMA window attention -> fp16 output
    {
        dim3 grid(BTOT, HEADS);
        attn_mma_kernel<<<grid, 128, ATTN_SMEM>>>(qkv, bm, a16);
    }

    // 5) Proj GEMM (fp16x2, fp32 out)
    {
        dim3 grid(4, 784);
        gemm_f16x2_mma<<<grid, 256, GEMM2_SMEM>>>(a16, wp16h, wp16l, b_proj, out,
                                                  DIM);
    }
}